// round 1
// baseline (speedup 1.0000x reference)
#include <cuda_runtime.h>
#include <math.h>

#define HIDDEN 1024
#define NE 16          // routed experts
#define NS 2           // shared experts
#define MID_R 256
#define MID_S 512
#define MAX_T 2048
#define BT 64
#define BN 64
#define BK 32
#define PADDED_CAP (MAX_T * 2 + NE * BT)   // 5120
#define N_TILES (PADDED_CAP / BT)          // 80

// ---------------- device scratch (static; no allocation) ----------------
__device__ float g_Hs[NS][MAX_T][MID_S];       // shared-expert hidden (silu(g)*u)
__device__ float g_Hr[PADDED_CAP][MID_R];      // routed hidden, expert-sorted+padded
__device__ float g_Y[PADDED_CAP][HIDDEN];      // routed down-proj, expert-sorted
__device__ int   g_topk_idx[MAX_T][2];
__device__ float g_topk_w[MAX_T][2];
__device__ int   g_counts[NE];
__device__ int   g_off[NE + 1];                // 64-aligned segment starts
__device__ int   g_cursor[NE];
__device__ int   g_perm[PADDED_CAP];           // sorted slot -> token (-1 = pad)
__device__ float g_pw[PADDED_CAP];             // sorted slot -> routing weight
__device__ int   g_token_pos[MAX_T][2];        // token -> its 2 sorted slots
__device__ int   g_tile_expert[N_TILES];       // GEMM tile -> expert id

// ---------------- init ----------------
__global__ void init_kernel() {
    int i = blockIdx.x * blockDim.x + threadIdx.x;
    if (i < PADDED_CAP) { g_perm[i] = -1; g_pw[i] = 0.f; }
    if (i < NE) { g_counts[i] = 0; g_cursor[i] = 0; }
}

// ---------------- router: one warp per token ----------------
__global__ void router_kernel(const float* __restrict__ x,
                              const float* __restrict__ rw, int T) {
    int warp = (blockIdx.x * blockDim.x + threadIdx.x) >> 5;
    int lane = threadIdx.x & 31;
    if (warp >= T) return;
    const float* xr = x + (size_t)warp * HIDDEN;

    float acc[NE];
#pragma unroll
    for (int e = 0; e < NE; e++) acc[e] = 0.f;

    for (int i = lane; i < HIDDEN; i += 32) {
        float xv = __ldg(xr + i);
        const float4* rp = (const float4*)(rw + (size_t)i * NE);
        float4 r0 = __ldg(rp + 0), r1 = __ldg(rp + 1);
        float4 r2 = __ldg(rp + 2), r3 = __ldg(rp + 3);
        acc[0]  += xv * r0.x; acc[1]  += xv * r0.y; acc[2]  += xv * r0.z; acc[3]  += xv * r0.w;
        acc[4]  += xv * r1.x; acc[5]  += xv * r1.y; acc[6]  += xv * r1.z; acc[7]  += xv * r1.w;
        acc[8]  += xv * r2.x; acc[9]  += xv * r2.y; acc[10] += xv * r2.z; acc[11] += xv * r2.w;
        acc[12] += xv * r3.x; acc[13] += xv * r3.y; acc[14] += xv * r3.z; acc[15] += xv * r3.w;
    }
#pragma unroll
    for (int e = 0; e < NE; e++) {
#pragma unroll
        for (int o = 16; o > 0; o >>= 1)
            acc[e] += __shfl_xor_sync(0xffffffffu, acc[e], o);
    }

    if (lane == 0) {
        float mx = acc[0];
#pragma unroll
        for (int e = 1; e < NE; e++) mx = fmaxf(mx, acc[e]);
        float p[NE], Z = 0.f;
#pragma unroll
        for (int e = 0; e < NE; e++) { p[e] = expf(acc[e] - mx); Z += p[e]; }
        // top-2 (stable: prefers lower index on ties, matching jax top_k)
        int i1 = 0; float v1 = p[0];
#pragma unroll
        for (int e = 1; e < NE; e++) if (p[e] > v1) { v1 = p[e]; i1 = e; }
        int i2 = -1; float v2 = -1.f;
#pragma unroll
        for (int e = 0; e < NE; e++)
            if (e != i1 && p[e] > v2) { v2 = p[e]; i2 = e; }
        v1 /= Z; v2 /= Z;
        float s = v1 + v2 + 1e-9f;
        g_topk_idx[warp][0] = i1; g_topk_idx[warp][1] = i2;
        g_topk_w[warp][0] = v1 / s; g_topk_w[warp][1] = v2 / s;
        atomicAdd(&g_counts[i1], 1);
        atomicAdd(&g_counts[i2], 1);
    }
}

// ---------------- scan: aligned offsets + tile->expert map ----------------
__global__ void scan_kernel() {
    if (threadIdx.x == 0) {
        int off = 0;
        for (int e = 0; e < NE; e++) {
            g_off[e] = off;
            int c = g_counts[e];
            off += ((c + BT - 1) / BT) * BT;
        }
        g_off[NE] = off;
        for (int t = 0; t < N_TILES; t++) {
            int r = t * BT;
            int e = NE - 1;
            for (int j = 0; j < NE; j++)
                if (r >= g_off[j] && r < g_off[j + 1]) e = j;
            g_tile_expert[t] = e;
        }
    }
}

// ---------------- scatter tokens to sorted slots ----------------
__global__ void scatter_kernel(int T) {
    int t = blockIdx.x * blockDim.x + threadIdx.x;
    if (t >= T) return;
#pragma unroll
    for (int k = 0; k < 2; k++) {
        int e = g_topk_idx[t][k];
        int pos = g_off[e] + atomicAdd(&g_cursor[e], 1);
        g_perm[pos] = t;
        g_pw[pos] = g_topk_w[t][k];
        g_token_pos[t][k] = pos;
    }
}

// ---------------- shared experts: fused gate+up dual GEMM ----------------
__global__ void __launch_bounds__(256)
gateup_shared_kernel(const float* __restrict__ x,
                     const float* __restrict__ wg_s,
                     const float* __restrict__ wu_s) {
    int n = blockIdx.z;
    int row0 = blockIdx.y * BT;
    int col0 = blockIdx.x * BN;
    const float* Wg = wg_s + (size_t)n * HIDDEN * MID_S;
    const float* Wu = wu_s + (size_t)n * HIDDEN * MID_S;

    __shared__ float As[BT][36];
    __shared__ float Bg[BK][BN];
    __shared__ float Bu[BK][BN];

    int tid = threadIdx.x;
    int tx = tid & 15, ty = tid >> 4;

    float accg[4][4], accu[4][4];
#pragma unroll
    for (int r = 0; r < 4; r++)
#pragma unroll
        for (int c = 0; c < 4; c++) { accg[r][c] = 0.f; accu[r][c] = 0.f; }

    for (int kk = 0; kk < HIDDEN; kk += BK) {
#pragma unroll
        for (int i = 0; i < 2; i++) {
            int idx = tid + 256 * i;
            int r = idx >> 3, c4 = (idx & 7) << 2;
            float4 v = *(const float4*)(x + (size_t)(row0 + r) * HIDDEN + kk + c4);
            *(float4*)&As[r][c4] = v;
        }
#pragma unroll
        for (int i = 0; i < 2; i++) {
            int idx = tid + 256 * i;
            int r = idx >> 4, c4 = (idx & 15) << 2;
            *(float4*)&Bg[r][c4] = *(const float4*)(Wg + (size_t)(kk + r) * MID_S + col0 + c4);
            *(float4*)&Bu[r][c4] = *(const float4*)(Wu + (size_t)(kk + r) * MID_S + col0 + c4);
        }
        __syncthreads();
#pragma unroll
        for (int k = 0; k < BK; k++) {
            float a[4];
#pragma unroll
            for (int r = 0; r < 4; r++) a[r] = As[ty * 4 + r][k];
            float4 bg = *(float4*)&Bg[k][tx * 4];
            float4 bu = *(float4*)&Bu[k][tx * 4];
#pragma unroll
            for (int r = 0; r < 4; r++) {
                accg[r][0] += a[r] * bg.x; accg[r][1] += a[r] * bg.y;
                accg[r][2] += a[r] * bg.z; accg[r][3] += a[r] * bg.w;
                accu[r][0] += a[r] * bu.x; accu[r][1] += a[r] * bu.y;
                accu[r][2] += a[r] * bu.z; accu[r][3] += a[r] * bu.w;
            }
        }
        __syncthreads();
    }
#pragma unroll
    for (int r = 0; r < 4; r++) {
        int row = row0 + ty * 4 + r;
        float* dst = &g_Hs[n][row][col0 + tx * 4];
#pragma unroll
        for (int c = 0; c < 4; c++) {
            float g = accg[r][c], u = accu[r][c];
            dst[c] = g / (1.f + __expf(-g)) * u;
        }
    }
}

// ---------------- routed experts: gathered fused gate+up dual GEMM ----------------
__global__ void __launch_bounds__(256)
gateup_routed_kernel(const float* __restrict__ x,
                     const float* __restrict__ wg_r,
                     const float* __restrict__ wu_r) {
    int tile = blockIdx.y;
    int row0 = tile * BT;
    int col0 = blockIdx.x * BN;
    int e = g_tile_expert[tile];
    const float* Wg = wg_r + (size_t)e * HIDDEN * MID_R;
    const float* Wu = wu_r + (size_t)e * HIDDEN * MID_R;

    __shared__ float As[BT][36];
    __shared__ float Bg[BK][BN];
    __shared__ float Bu[BK][BN];
    __shared__ int   s_perm[BT];
    __shared__ float s_pw[BT];

    int tid = threadIdx.x;
    int tx = tid & 15, ty = tid >> 4;
    if (tid < BT) { s_perm[tid] = g_perm[row0 + tid]; s_pw[tid] = g_pw[row0 + tid]; }
    __syncthreads();

    float accg[4][4], accu[4][4];
#pragma unroll
    for (int r = 0; r < 4; r++)
#pragma unroll
        for (int c = 0; c < 4; c++) { accg[r][c] = 0.f; accu[r][c] = 0.f; }

    for (int kk = 0; kk < HIDDEN; kk += BK) {
#pragma unroll
        for (int i = 0; i < 2; i++) {
            int idx = tid + 256 * i;
            int r = idx >> 3, c4 = (idx & 7) << 2;
            int grow = s_perm[r];
            float4 v = make_float4(0.f, 0.f, 0.f, 0.f);
            if (grow >= 0)
                v = *(const float4*)(x + (size_t)grow * HIDDEN + kk + c4);
            *(float4*)&As[r][c4] = v;
        }
#pragma unroll
        for (int i = 0; i < 2; i++) {
            int idx = tid + 256 * i;
            int r = idx >> 4, c4 = (idx & 15) << 2;
            *(float4*)&Bg[r][c4] = *(const float4*)(Wg + (size_t)(kk + r) * MID_R + col0 + c4);
            *(float4*)&Bu[r][c4] = *(const float4*)(Wu + (size_t)(kk + r) * MID_R + col0 + c4);
        }
        __syncthreads();
#pragma unroll
        for (int k = 0; k < BK; k++) {
            float a[4];
#pragma unroll
            for (int r = 0; r < 4; r++) a[r] = As[ty * 4 + r][k];
            float4 bg = *(float4*)&Bg[k][tx * 4];
            float4 bu = *(float4*)&Bu[k][tx * 4];
#pragma unroll
            for (int r = 0; r < 4; r++) {
                accg[r][0] += a[r] * bg.x; accg[r][1] += a[r] * bg.y;
                accg[r][2] += a[r] * bg.z; accg[r][3] += a[r] * bg.w;
                accu[r][0] += a[r] * bu.x; accu[r][1] += a[r] * bu.y;
                accu[r][2] += a[r] * bu.z; accu[r][3] += a[r] * bu.w;
            }
        }
        __syncthreads();
    }
#pragma unroll
    for (int r = 0; r < 4; r++) {
        int lrow = ty * 4 + r;
        float w = s_pw[lrow];
        float* dst = &g_Hr[row0 + lrow][col0 + tx * 4];
#pragma unroll
        for (int c = 0; c < 4; c++) {
            float g = accg[r][c], u = accu[r][c];
            dst[c] = g / (1.f + __expf(-g)) * u * w;
        }
    }
}

// ---------------- routed down-proj into sorted scratch Y ----------------
__global__ void __launch_bounds__(256)
down_routed_kernel(const float* __restrict__ wd_r) {
    int tile = blockIdx.y;
    int row0 = tile * BT;
    int col0 = blockIdx.x * BN;
    int e = g_tile_expert[tile];
    const float* Wd = wd_r + (size_t)e * MID_R * HIDDEN;

    __shared__ float As[BT][36];
    __shared__ float Bs[BK][BN];

    int tid = threadIdx.x;
    int tx = tid & 15, ty = tid >> 4;

    float acc[4][4];
#pragma unroll
    for (int r = 0; r < 4; r++)
#pragma unroll
        for (int c = 0; c < 4; c++) acc[r][c] = 0.f;

    for (int kk = 0; kk < MID_R; kk += BK) {
#pragma unroll
        for (int i = 0; i < 2; i++) {
            int idx = tid + 256 * i;
            int r = idx >> 3, c4 = (idx & 7) << 2;
            *(float4*)&As[r][c4] = *(const float4*)&g_Hr[row0 + r][kk + c4];
        }
#pragma unroll
        for (int i = 0; i < 2; i++) {
            int idx = tid + 256 * i;
            int r = idx >> 4, c4 = (idx & 15) << 2;
            *(float4*)&Bs[r][c4] = *(const float4*)(Wd + (size_t)(kk + r) * HIDDEN + col0 + c4);
        }
        __syncthreads();
#pragma unroll
        for (int k = 0; k < BK; k++) {
            float a[4];
#pragma unroll
            for (int r = 0; r < 4; r++) a[r] = As[ty * 4 + r][k];
            float4 b = *(float4*)&Bs[k][tx * 4];
#pragma unroll
            for (int r = 0; r < 4; r++) {
                acc[r][0] += a[r] * b.x; acc[r][1] += a[r] * b.y;
                acc[r][2] += a[r] * b.z; acc[r][3] += a[r] * b.w;
            }
        }
        __syncthreads();
    }
#pragma unroll
    for (int r = 0; r < 4; r++) {
        float* dst = &g_Y[row0 + ty * 4 + r][col0 + tx * 4];
        float4 o = make_float4(acc[r][0], acc[r][1], acc[r][2], acc[r][3]);
        *(float4*)dst = o;
    }
}

// ---------------- shared down-proj + routed combine -> out ----------------
__global__ void __launch_bounds__(256)
down_shared_kernel(const float* __restrict__ wd_s, float* __restrict__ out) {
    int row0 = blockIdx.y * BT;
    int col0 = blockIdx.x * BN;

    __shared__ float As[BT][36];
    __shared__ float Bs[BK][BN];
    __shared__ int s_p0[BT], s_p1[BT];

    int tid = threadIdx.x;
    int tx = tid & 15, ty = tid >> 4;
    if (tid < BT) {
        s_p0[tid] = g_token_pos[row0 + tid][0];
        s_p1[tid] = g_token_pos[row0 + tid][1];
    }

    float acc[4][4];
#pragma unroll
    for (int r = 0; r < 4; r++)
#pragma unroll
        for (int c = 0; c < 4; c++) acc[r][c] = 0.f;

    for (int n = 0; n < NS; n++) {
        const float* Wd = wd_s + (size_t)n * MID_S * HIDDEN;
        for (int kk = 0; kk < MID_S; kk += BK) {
            __syncthreads();
#pragma unroll
            for (int i = 0; i < 2; i++) {
                int idx = tid + 256 * i;
                int r = idx >> 3, c4 = (idx & 7) << 2;
                *(float4*)&As[r][c4] = *(const float4*)&g_Hs[n][row0 + r][kk + c4];
            }
#pragma unroll
            for (int i = 0; i < 2; i++) {
                int idx = tid + 256 * i;
                int r = idx >> 4, c4 = (idx & 15) << 2;
                *(float4*)&Bs[r][c4] = *(const float4*)(Wd + (size_t)(kk + r) * HIDDEN + col0 + c4);
            }
            __syncthreads();
#pragma unroll
            for (int k = 0; k < BK; k++) {
                float a[4];
#pragma unroll
                for (int r = 0; r < 4; r++) a[r] = As[ty * 4 + r][k];
                float4 b = *(float4*)&Bs[k][tx * 4];
#pragma unroll
                for (int r = 0; r < 4; r++) {
                    acc[r][0] += a[r] * b.x; acc[r][1] += a[r] * b.y;
                    acc[r][2] += a[r] * b.z; acc[r][3] += a[r] * b.w;
                }
            }
        }
    }
    __syncthreads();
#pragma unroll
    for (int r = 0; r < 4; r++) {
        int lrow = ty * 4 + r;
        int row = row0 + lrow;
        int p0 = s_p0[lrow], p1 = s_p1[lrow];
        float4 y0 = *(const float4*)&g_Y[p0][col0 + tx * 4];
        float4 y1 = *(const float4*)&g_Y[p1][col0 + tx * 4];
        float4 o;
        o.x = acc[r][0] + y0.x + y1.x;
        o.y = acc[r][1] + y0.y + y1.y;
        o.z = acc[r][2] + y0.z + y1.z;
        o.w = acc[r][3] + y0.w + y1.w;
        *(float4*)(out + (size_t)row * HIDDEN + col0 + tx * 4) = o;
    }
}

// ---------------- launch ----------------
extern "C" void kernel_launch(void* const* d_in, const int* in_sizes, int n_in,
                              void* d_out, int out_size) {
    const float* x    = (const float*)d_in[0];
    const float* rw   = (const float*)d_in[1];
    const float* wg_r = (const float*)d_in[2];
    const float* wu_r = (const float*)d_in[3];
    const float* wd_r = (const float*)d_in[4];
    const float* wg_s = (const float*)d_in[5];
    const float* wu_s = (const float*)d_in[6];
    const float* wd_s = (const float*)d_in[7];
    float* out = (float*)d_out;

    int T = in_sizes[0] / HIDDEN;
    if (T > MAX_T || T % BT != 0) return;  // scratch sized for the dataset shape

    init_kernel<<<(PADDED_CAP + 255) / 256, 256>>>();
    router_kernel<<<(T + 7) / 8, 256>>>(x, rw, T);
    scan_kernel<<<1, 32>>>();
    scatter_kernel<<<(T + 255) / 256, 256>>>(T);

    dim3 ggs(MID_S / BN, T / BT, NS);
    gateup_shared_kernel<<<ggs, 256>>>(x, wg_s, wu_s);

    dim3 ggr(MID_R / BN, N_TILES);
    gateup_routed_kernel<<<ggr, 256>>>(x, wg_r, wu_r);

    dim3 gdr(HIDDEN / BN, N_TILES);
    down_routed_kernel<<<gdr, 256>>>(wd_r);

    dim3 gds(HIDDEN / BN, T / BT);
    down_shared_kernel<<<gds, 256>>>(wd_s, out);
}

// round 2
// speedup vs baseline: 2.0552x; 2.0552x over previous
#include <cuda_runtime.h>
#include <math.h>

#define HIDDEN 1024
#define NE 16
#define NS 2
#define MID_R 256
#define MID_S 512
#define MAX_T 2048
#define BT 64
#define PADDED_CAP (MAX_T * 2 + NE * BT)   // 5120
#define N_TILES (PADDED_CAP / BT)          // 80

#define SA 36   // A smem stride (floats): bank = (4m + k) % 32, conflict-free
#define SB 68   // B smem stride (floats): bank = (4k + n) % 32, conflict-free

// ---------------- device scratch ----------------
__device__ float g_Hs[NS][MAX_T][MID_S];
__device__ float g_Hr[PADDED_CAP][MID_R];
__device__ float g_Y[PADDED_CAP][HIDDEN];
__device__ int   g_topk_idx[MAX_T][2];
__device__ float g_topk_w[MAX_T][2];
__device__ int   g_counts[NE];
__device__ int   g_off[NE + 1];
__device__ int   g_cursor[NE];
__device__ int   g_perm[PADDED_CAP];
__device__ float g_pw[PADDED_CAP];
__device__ int   g_token_pos[MAX_T][2];
__device__ int   g_tile_expert[N_TILES];

// ---------------- helpers ----------------
__device__ __forceinline__ unsigned tf32cvt(float f) {
    unsigned u;
    asm("cvt.rna.tf32.f32 %0, %1;" : "=r"(u) : "f"(f));
    return u;
}

__device__ __forceinline__ void mma8(float* c, const unsigned* a, const unsigned* b) {
    asm volatile(
        "mma.sync.aligned.m16n8k8.row.col.f32.tf32.tf32.f32 "
        "{%0,%1,%2,%3},{%4,%5,%6,%7},{%8,%9},{%0,%1,%2,%3};"
        : "+f"(c[0]), "+f"(c[1]), "+f"(c[2]), "+f"(c[3])
        : "r"(a[0]), "r"(a[1]), "r"(a[2]), "r"(a[3]), "r"(b[0]), "r"(b[1]));
}

__device__ __forceinline__ float silu(float g) { return g / (1.f + __expf(-g)); }

// ---------------- init ----------------
__global__ void init_kernel() {
    int i = blockIdx.x * blockDim.x + threadIdx.x;
    if (i < PADDED_CAP) { g_perm[i] = -1; g_pw[i] = 0.f; }
    if (i < NE) { g_counts[i] = 0; g_cursor[i] = 0; }
}

// ---------------- router (exact fp32; one warp per token) ----------------
__global__ void router_kernel(const float* __restrict__ x,
                              const float* __restrict__ rw, int T) {
    int warp = (blockIdx.x * blockDim.x + threadIdx.x) >> 5;
    int lane = threadIdx.x & 31;
    if (warp >= T) return;
    const float* xr = x + (size_t)warp * HIDDEN;

    float acc[NE];
#pragma unroll
    for (int e = 0; e < NE; e++) acc[e] = 0.f;

    for (int i = lane; i < HIDDEN; i += 32) {
        float xv = __ldg(xr + i);
        const float4* rp = (const float4*)(rw + (size_t)i * NE);
        float4 r0 = __ldg(rp + 0), r1 = __ldg(rp + 1);
        float4 r2 = __ldg(rp + 2), r3 = __ldg(rp + 3);
        acc[0]  += xv * r0.x; acc[1]  += xv * r0.y; acc[2]  += xv * r0.z; acc[3]  += xv * r0.w;
        acc[4]  += xv * r1.x; acc[5]  += xv * r1.y; acc[6]  += xv * r1.z; acc[7]  += xv * r1.w;
        acc[8]  += xv * r2.x; acc[9]  += xv * r2.y; acc[10] += xv * r2.z; acc[11] += xv * r2.w;
        acc[12] += xv * r3.x; acc[13] += xv * r3.y; acc[14] += xv * r3.z; acc[15] += xv * r3.w;
    }
#pragma unroll
    for (int e = 0; e < NE; e++) {
#pragma unroll
        for (int o = 16; o > 0; o >>= 1)
            acc[e] += __shfl_xor_sync(0xffffffffu, acc[e], o);
    }

    if (lane == 0) {
        float mx = acc[0];
#pragma unroll
        for (int e = 1; e < NE; e++) mx = fmaxf(mx, acc[e]);
        float p[NE], Z = 0.f;
#pragma unroll
        for (int e = 0; e < NE; e++) { p[e] = expf(acc[e] - mx); Z += p[e]; }
        int i1 = 0; float v1 = p[0];
#pragma unroll
        for (int e = 1; e < NE; e++) if (p[e] > v1) { v1 = p[e]; i1 = e; }
        int i2 = -1; float v2 = -1.f;
#pragma unroll
        for (int e = 0; e < NE; e++)
            if (e != i1 && p[e] > v2) { v2 = p[e]; i2 = e; }
        v1 /= Z; v2 /= Z;
        float s = v1 + v2 + 1e-9f;
        g_topk_idx[warp][0] = i1; g_topk_idx[warp][1] = i2;
        g_topk_w[warp][0] = v1 / s; g_topk_w[warp][1] = v2 / s;
        atomicAdd(&g_counts[i1], 1);
        atomicAdd(&g_counts[i2], 1);
    }
}

// ---------------- scan ----------------
__global__ void scan_kernel() {
    if (threadIdx.x == 0) {
        int off = 0;
        for (int e = 0; e < NE; e++) {
            g_off[e] = off;
            int c = g_counts[e];
            off += ((c + BT - 1) / BT) * BT;
        }
        g_off[NE] = off;
        for (int t = 0; t < N_TILES; t++) {
            int r = t * BT;
            int e = NE - 1;
            for (int j = 0; j < NE; j++)
                if (r >= g_off[j] && r < g_off[j + 1]) e = j;
            g_tile_expert[t] = e;
        }
    }
}

// ---------------- scatter ----------------
__global__ void scatter_kernel(int T) {
    int t = blockIdx.x * blockDim.x + threadIdx.x;
    if (t >= T) return;
#pragma unroll
    for (int k = 0; k < 2; k++) {
        int e = g_topk_idx[t][k];
        int pos = g_off[e] + atomicAdd(&g_cursor[e], 1);
        g_perm[pos] = t;
        g_pw[pos] = g_topk_w[t][k];
        g_token_pos[t][k] = pos;
    }
}

// =======================================================================
// Tensor-core GEMMs: 128 threads / 4 warps, 64x64 block tile, 32x32/warp,
// BK=32, tf32 mma.sync.m16n8k8, fp32 accumulate.
// Warp w: wr=w>>1 row half, wc=w&1 col half.
// =======================================================================

// ---------------- shared experts gate+up (dual GEMM) ----------------
__global__ void __launch_bounds__(128)
gateup_shared_k(const float* __restrict__ x,
                const float* __restrict__ wg_s,
                const float* __restrict__ wu_s) {
    int n = blockIdx.z;
    int row0 = blockIdx.y * 64;
    int col0 = blockIdx.x * 64;
    const float* Wg = wg_s + (size_t)n * HIDDEN * MID_S;
    const float* Wu = wu_s + (size_t)n * HIDDEN * MID_S;

    __shared__ unsigned As[64 * SA];
    __shared__ unsigned Bg[32 * SB];
    __shared__ unsigned Bu[32 * SB];

    int tid = threadIdx.x, lane = tid & 31, w = tid >> 5;
    int wr = w >> 1, wc = w & 1;

    float accg[2][4][4] = {}, accu[2][4][4] = {};

    for (int kk = 0; kk < HIDDEN; kk += 32) {
#pragma unroll
        for (int i = 0; i < 4; i++) {  // A: 64x32 = 512 float4
            int idx = tid + 128 * i;
            int r = idx >> 3, c4 = (idx & 7) << 2;
            float4 v = *(const float4*)(x + (size_t)(row0 + r) * HIDDEN + kk + c4);
            unsigned* d = &As[r * SA + c4];
            d[0] = tf32cvt(v.x); d[1] = tf32cvt(v.y); d[2] = tf32cvt(v.z); d[3] = tf32cvt(v.w);
        }
#pragma unroll
        for (int i = 0; i < 4; i++) {  // B: 32x64 each
            int idx = tid + 128 * i;
            int r = idx >> 4, c4 = (idx & 15) << 2;
            float4 vg = *(const float4*)(Wg + (size_t)(kk + r) * MID_S + col0 + c4);
            float4 vu = *(const float4*)(Wu + (size_t)(kk + r) * MID_S + col0 + c4);
            unsigned* dg = &Bg[r * SB + c4];
            dg[0] = tf32cvt(vg.x); dg[1] = tf32cvt(vg.y); dg[2] = tf32cvt(vg.z); dg[3] = tf32cvt(vg.w);
            unsigned* du = &Bu[r * SB + c4];
            du[0] = tf32cvt(vu.x); du[1] = tf32cvt(vu.y); du[2] = tf32cvt(vu.z); du[3] = tf32cvt(vu.w);
        }
        __syncthreads();
#pragma unroll
        for (int ks = 0; ks < 4; ks++) {
            int k0 = ks * 8;
            unsigned a[2][4];
#pragma unroll
            for (int rt = 0; rt < 2; rt++) {
                const unsigned* p = &As[(wr * 32 + rt * 16 + (lane >> 2)) * SA + k0 + (lane & 3)];
                a[rt][0] = p[0]; a[rt][1] = p[8 * SA]; a[rt][2] = p[4]; a[rt][3] = p[8 * SA + 4];
            }
            unsigned bg[4][2], bu[4][2];
#pragma unroll
            for (int ct = 0; ct < 4; ct++) {
                int ncol = wc * 32 + ct * 8 + (lane >> 2);
                const unsigned* pg = &Bg[(k0 + (lane & 3)) * SB + ncol];
                bg[ct][0] = pg[0]; bg[ct][1] = pg[4 * SB];
                const unsigned* pu = &Bu[(k0 + (lane & 3)) * SB + ncol];
                bu[ct][0] = pu[0]; bu[ct][1] = pu[4 * SB];
            }
#pragma unroll
            for (int rt = 0; rt < 2; rt++)
#pragma unroll
                for (int ct = 0; ct < 4; ct++) {
                    mma8(accg[rt][ct], a[rt], bg[ct]);
                    mma8(accu[rt][ct], a[rt], bu[ct]);
                }
        }
        __syncthreads();
    }
#pragma unroll
    for (int rt = 0; rt < 2; rt++) {
        int r0 = row0 + wr * 32 + rt * 16 + (lane >> 2);
#pragma unroll
        for (int ct = 0; ct < 4; ct++) {
            int c = col0 + wc * 32 + ct * 8 + 2 * (lane & 3);
            float* gg = accg[rt][ct];
            float* uu = accu[rt][ct];
            float2 h0 = make_float2(silu(gg[0]) * uu[0], silu(gg[1]) * uu[1]);
            float2 h1 = make_float2(silu(gg[2]) * uu[2], silu(gg[3]) * uu[3]);
            *(float2*)&g_Hs[n][r0][c] = h0;
            *(float2*)&g_Hs[n][r0 + 8][c] = h1;
        }
    }
}

// ---------------- routed gate+up (gathered A, weight in epilogue) ----------------
__global__ void __launch_bounds__(128)
gateup_routed_k(const float* __restrict__ x,
                const float* __restrict__ wg_r,
                const float* __restrict__ wu_r) {
    int tile = blockIdx.y;
    int row0 = tile * 64;
    int col0 = blockIdx.x * 64;
    int e = g_tile_expert[tile];
    const float* Wg = wg_r + (size_t)e * HIDDEN * MID_R;
    const float* Wu = wu_r + (size_t)e * HIDDEN * MID_R;

    __shared__ unsigned As[64 * SA];
    __shared__ unsigned Bg[32 * SB];
    __shared__ unsigned Bu[32 * SB];
    __shared__ int   s_perm[64];
    __shared__ float s_pw[64];

    int tid = threadIdx.x, lane = tid & 31, w = tid >> 5;
    int wr = w >> 1, wc = w & 1;
    if (tid < 64) { s_perm[tid] = g_perm[row0 + tid]; s_pw[tid] = g_pw[row0 + tid]; }
    __syncthreads();

    float accg[2][4][4] = {}, accu[2][4][4] = {};

    for (int kk = 0; kk < HIDDEN; kk += 32) {
#pragma unroll
        for (int i = 0; i < 4; i++) {
            int idx = tid + 128 * i;
            int r = idx >> 3, c4 = (idx & 7) << 2;
            int grow = s_perm[r];
            float4 v = make_float4(0.f, 0.f, 0.f, 0.f);
            if (grow >= 0)
                v = *(const float4*)(x + (size_t)grow * HIDDEN + kk + c4);
            unsigned* d = &As[r * SA + c4];
            d[0] = tf32cvt(v.x); d[1] = tf32cvt(v.y); d[2] = tf32cvt(v.z); d[3] = tf32cvt(v.w);
        }
#pragma unroll
        for (int i = 0; i < 4; i++) {
            int idx = tid + 128 * i;
            int r = idx >> 4, c4 = (idx & 15) << 2;
            float4 vg = *(const float4*)(Wg + (size_t)(kk + r) * MID_R + col0 + c4);
            float4 vu = *(const float4*)(Wu + (size_t)(kk + r) * MID_R + col0 + c4);
            unsigned* dg = &Bg[r * SB + c4];
            dg[0] = tf32cvt(vg.x); dg[1] = tf32cvt(vg.y); dg[2] = tf32cvt(vg.z); dg[3] = tf32cvt(vg.w);
            unsigned* du = &Bu[r * SB + c4];
            du[0] = tf32cvt(vu.x); du[1] = tf32cvt(vu.y); du[2] = tf32cvt(vu.z); du[3] = tf32cvt(vu.w);
        }
        __syncthreads();
#pragma unroll
        for (int ks = 0; ks < 4; ks++) {
            int k0 = ks * 8;
            unsigned a[2][4];
#pragma unroll
            for (int rt = 0; rt < 2; rt++) {
                const unsigned* p = &As[(wr * 32 + rt * 16 + (lane >> 2)) * SA + k0 + (lane & 3)];
                a[rt][0] = p[0]; a[rt][1] = p[8 * SA]; a[rt][2] = p[4]; a[rt][3] = p[8 * SA + 4];
            }
            unsigned bg[4][2], bu[4][2];
#pragma unroll
            for (int ct = 0; ct < 4; ct++) {
                int ncol = wc * 32 + ct * 8 + (lane >> 2);
                const unsigned* pg = &Bg[(k0 + (lane & 3)) * SB + ncol];
                bg[ct][0] = pg[0]; bg[ct][1] = pg[4 * SB];
                const unsigned* pu = &Bu[(k0 + (lane & 3)) * SB + ncol];
                bu[ct][0] = pu[0]; bu[ct][1] = pu[4 * SB];
            }
#pragma unroll
            for (int rt = 0; rt < 2; rt++)
#pragma unroll
                for (int ct = 0; ct < 4; ct++) {
                    mma8(accg[rt][ct], a[rt], bg[ct]);
                    mma8(accu[rt][ct], a[rt], bu[ct]);
                }
        }
        __syncthreads();
    }
#pragma unroll
    for (int rt = 0; rt < 2; rt++) {
        int lr = wr * 32 + rt * 16 + (lane >> 2);
        float w0 = s_pw[lr], w1 = s_pw[lr + 8];
#pragma unroll
        for (int ct = 0; ct < 4; ct++) {
            int c = col0 + wc * 32 + ct * 8 + 2 * (lane & 3);
            float* gg = accg[rt][ct];
            float* uu = accu[rt][ct];
            float2 h0 = make_float2(silu(gg[0]) * uu[0] * w0, silu(gg[1]) * uu[1] * w0);
            float2 h1 = make_float2(silu(gg[2]) * uu[2] * w1, silu(gg[3]) * uu[3] * w1);
            *(float2*)&g_Hr[row0 + lr][c] = h0;
            *(float2*)&g_Hr[row0 + lr + 8][c] = h1;
        }
    }
}

// ---------------- routed down-proj -> g_Y ----------------
__global__ void __launch_bounds__(128)
down_routed_k(const float* __restrict__ wd_r) {
    int tile = blockIdx.y;
    int row0 = tile * 64;
    int col0 = blockIdx.x * 64;
    int e = g_tile_expert[tile];
    const float* Wd = wd_r + (size_t)e * MID_R * HIDDEN;

    __shared__ unsigned As[64 * SA];
    __shared__ unsigned Bs[32 * SB];

    int tid = threadIdx.x, lane = tid & 31, w = tid >> 5;
    int wr = w >> 1, wc = w & 1;

    float acc[2][4][4] = {};

    for (int kk = 0; kk < MID_R; kk += 32) {
#pragma unroll
        for (int i = 0; i < 4; i++) {
            int idx = tid + 128 * i;
            int r = idx >> 3, c4 = (idx & 7) << 2;
            float4 v = *(const float4*)&g_Hr[row0 + r][kk + c4];
            unsigned* d = &As[r * SA + c4];
            d[0] = tf32cvt(v.x); d[1] = tf32cvt(v.y); d[2] = tf32cvt(v.z); d[3] = tf32cvt(v.w);
        }
#pragma unroll
        for (int i = 0; i < 4; i++) {
            int idx = tid + 128 * i;
            int r = idx >> 4, c4 = (idx & 15) << 2;
            float4 vb = *(const float4*)(Wd + (size_t)(kk + r) * HIDDEN + col0 + c4);
            unsigned* db = &Bs[r * SB + c4];
            db[0] = tf32cvt(vb.x); db[1] = tf32cvt(vb.y); db[2] = tf32cvt(vb.z); db[3] = tf32cvt(vb.w);
        }
        __syncthreads();
#pragma unroll
        for (int ks = 0; ks < 4; ks++) {
            int k0 = ks * 8;
            unsigned a[2][4];
#pragma unroll
            for (int rt = 0; rt < 2; rt++) {
                const unsigned* p = &As[(wr * 32 + rt * 16 + (lane >> 2)) * SA + k0 + (lane & 3)];
                a[rt][0] = p[0]; a[rt][1] = p[8 * SA]; a[rt][2] = p[4]; a[rt][3] = p[8 * SA + 4];
            }
            unsigned b[4][2];
#pragma unroll
            for (int ct = 0; ct < 4; ct++) {
                int ncol = wc * 32 + ct * 8 + (lane >> 2);
                const unsigned* pb = &Bs[(k0 + (lane & 3)) * SB + ncol];
                b[ct][0] = pb[0]; b[ct][1] = pb[4 * SB];
            }
#pragma unroll
            for (int rt = 0; rt < 2; rt++)
#pragma unroll
                for (int ct = 0; ct < 4; ct++)
                    mma8(acc[rt][ct], a[rt], b[ct]);
        }
        __syncthreads();
    }
#pragma unroll
    for (int rt = 0; rt < 2; rt++) {
        int r0 = row0 + wr * 32 + rt * 16 + (lane >> 2);
#pragma unroll
        for (int ct = 0; ct < 4; ct++) {
            int c = col0 + wc * 32 + ct * 8 + 2 * (lane & 3);
            *(float2*)&g_Y[r0][c] = make_float2(acc[rt][ct][0], acc[rt][ct][1]);
            *(float2*)&g_Y[r0 + 8][c] = make_float2(acc[rt][ct][2], acc[rt][ct][3]);
        }
    }
}

// ---------------- shared down-proj + routed combine -> out ----------------
__global__ void __launch_bounds__(128)
down_shared_k(const float* __restrict__ wd_s, float* __restrict__ out) {
    int row0 = blockIdx.y * 64;
    int col0 = blockIdx.x * 64;

    __shared__ unsigned As[64 * SA];
    __shared__ unsigned Bs[32 * SB];
    __shared__ int s_p0[64], s_p1[64];

    int tid = threadIdx.x, lane = tid & 31, w = tid >> 5;
    int wr = w >> 1, wc = w & 1;
    if (tid < 64) {
        s_p0[tid] = g_token_pos[row0 + tid][0];
        s_p1[tid] = g_token_pos[row0 + tid][1];
    }

    float acc[2][4][4] = {};

    for (int n = 0; n < NS; n++) {
        const float* Wd = wd_s + (size_t)n * MID_S * HIDDEN;
        for (int kk = 0; kk < MID_S; kk += 32) {
            __syncthreads();
#pragma unroll
            for (int i = 0; i < 4; i++) {
                int idx = tid + 128 * i;
                int r = idx >> 3, c4 = (idx & 7) << 2;
                float4 v = *(const float4*)&g_Hs[n][row0 + r][kk + c4];
                unsigned* d = &As[r * SA + c4];
                d[0] = tf32cvt(v.x); d[1] = tf32cvt(v.y); d[2] = tf32cvt(v.z); d[3] = tf32cvt(v.w);
            }
#pragma unroll
            for (int i = 0; i < 4; i++) {
                int idx = tid + 128 * i;
                int r = idx >> 4, c4 = (idx & 15) << 2;
                float4 vb = *(const float4*)(Wd + (size_t)(kk + r) * HIDDEN + col0 + c4);
                unsigned* db = &Bs[r * SB + c4];
                db[0] = tf32cvt(vb.x); db[1] = tf32cvt(vb.y); db[2] = tf32cvt(vb.z); db[3] = tf32cvt(vb.w);
            }
            __syncthreads();
#pragma unroll
            for (int ks = 0; ks < 4; ks++) {
                int k0 = ks * 8;
                unsigned a[2][4];
#pragma unroll
                for (int rt = 0; rt < 2; rt++) {
                    const unsigned* p = &As[(wr * 32 + rt * 16 + (lane >> 2)) * SA + k0 + (lane & 3)];
                    a[rt][0] = p[0]; a[rt][1] = p[8 * SA]; a[rt][2] = p[4]; a[rt][3] = p[8 * SA + 4];
                }
                unsigned b[4][2];
#pragma unroll
                for (int ct = 0; ct < 4; ct++) {
                    int ncol = wc * 32 + ct * 8 + (lane >> 2);
                    const unsigned* pb = &Bs[(k0 + (lane & 3)) * SB + ncol];
                    b[ct][0] = pb[0]; b[ct][1] = pb[4 * SB];
                }
#pragma unroll
                for (int rt = 0; rt < 2; rt++)
#pragma unroll
                    for (int ct = 0; ct < 4; ct++)
                        mma8(acc[rt][ct], a[rt], b[ct]);
            }
        }
    }
    __syncthreads();
#pragma unroll
    for (int rt = 0; rt < 2; rt++) {
        int lr = wr * 32 + rt * 16 + (lane >> 2);
        int r0 = row0 + lr;
        int p0a = s_p0[lr], p1a = s_p1[lr];
        int p0b = s_p0[lr + 8], p1b = s_p1[lr + 8];
#pragma unroll
        for (int ct = 0; ct < 4; ct++) {
            int c = col0 + wc * 32 + ct * 8 + 2 * (lane & 3);
            float2 ya = *(const float2*)&g_Y[p0a][c];
            float2 yb = *(const float2*)&g_Y[p1a][c];
            float2 o0 = make_float2(acc[rt][ct][0] + ya.x + yb.x,
                                    acc[rt][ct][1] + ya.y + yb.y);
            *(float2*)(out + (size_t)r0 * HIDDEN + c) = o0;
            float2 yc = *(const float2*)&g_Y[p0b][c];
            float2 yd = *(const float2*)&g_Y[p1b][c];
            float2 o1 = make_float2(acc[rt][ct][2] + yc.x + yd.x,
                                    acc[rt][ct][3] + yc.y + yd.y);
            *(float2*)(out + (size_t)(r0 + 8) * HIDDEN + c) = o1;
        }
    }
}

// ---------------- launch ----------------
extern "C" void kernel_launch(void* const* d_in, const int* in_sizes, int n_in,
                              void* d_out, int out_size) {
    const float* x    = (const float*)d_in[0];
    const float* rw   = (const float*)d_in[1];
    const float* wg_r = (const float*)d_in[2];
    const float* wu_r = (const float*)d_in[3];
    const float* wd_r = (const float*)d_in[4];
    const float* wg_s = (const float*)d_in[5];
    const float* wu_s = (const float*)d_in[6];
    const float* wd_s = (const float*)d_in[7];
    float* out = (float*)d_out;

    int T = in_sizes[0] / HIDDEN;
    if (T > MAX_T || T % 64 != 0) return;

    init_kernel<<<(PADDED_CAP + 255) / 256, 256>>>();
    router_kernel<<<(T + 7) / 8, 256>>>(x, rw, T);
    scan_kernel<<<1, 32>>>();
    scatter_kernel<<<(T + 255) / 256, 256>>>(T);

    dim3 ggs(MID_S / 64, T / 64, NS);
    gateup_shared_k<<<ggs, 128>>>(x, wg_s, wu_s);

    dim3 ggr(MID_R / 64, N_TILES);
    gateup_routed_k<<<ggr, 128>>>(x, wg_r, wu_r);

    dim3 gdr(HIDDEN / 64, N_TILES);
    down_routed_k<<<gdr, 128>>>(wd_r);

    dim3 gds(HIDDEN / 64, T / 64);
    down_shared_k<<<gds, 128>>>(wd_s, out);
}

// round 4
// speedup vs baseline: 2.0957x; 1.0197x over previous
#include <cuda_runtime.h>
#include <math.h>

#define HIDDEN 1024
#define NE 16
#define NS 2
#define MID_R 256
#define MID_S 512
#define MAX_T 2048
#define BT 128                              // expert segment alignment = GEMM row tile
#define PADDED_CAP (MAX_T * 2 + NE * BT)    // 6144
#define N_TILES (PADDED_CAP / BT)           // 48

#define SA 36   // A smem stride (floats)
#define SB 68   // B smem stride (floats)

// ---------------- device scratch ----------------
__device__ float g_Hs[NS][MAX_T][MID_S];
__device__ float g_Hr[PADDED_CAP][MID_R];
__device__ float g_Y[PADDED_CAP][HIDDEN];
__device__ int   g_topk_idx[MAX_T][2];
__device__ float g_topk_w[MAX_T][2];
__device__ int   g_counts[NE];
__device__ int   g_off[NE + 1];
__device__ int   g_cursor[NE];
__device__ int   g_perm[PADDED_CAP];
__device__ float g_pw[PADDED_CAP];
__device__ int   g_token_pos[MAX_T][2];
__device__ int   g_tile_expert[N_TILES];

// ---------------- helpers ----------------
__device__ __forceinline__ unsigned tf32cvt(float f) {
    unsigned u;
    asm("cvt.rna.tf32.f32 %0, %1;" : "=r"(u) : "f"(f));
    return u;
}

__device__ __forceinline__ void mma8(float* c, const unsigned* a, const unsigned* b) {
    asm volatile(
        "mma.sync.aligned.m16n8k8.row.col.f32.tf32.tf32.f32 "
        "{%0,%1,%2,%3},{%4,%5,%6,%7},{%8,%9},{%0,%1,%2,%3};"
        : "+f"(c[0]), "+f"(c[1]), "+f"(c[2]), "+f"(c[3])
        : "r"(a[0]), "r"(a[1]), "r"(a[2]), "r"(a[3]), "r"(b[0]), "r"(b[1]));
}

__device__ __forceinline__ float silu(float g) { return g / (1.f + __expf(-g)); }

__device__ __forceinline__ void cvst4(unsigned* d, float4 v) {
    d[0] = tf32cvt(v.x); d[1] = tf32cvt(v.y); d[2] = tf32cvt(v.z); d[3] = tf32cvt(v.w);
}

// ---------------- init ----------------
__global__ void init_kernel() {
    int i = blockIdx.x * blockDim.x + threadIdx.x;
    if (i < PADDED_CAP) { g_perm[i] = -1; g_pw[i] = 0.f; }
    if (i < NE) { g_counts[i] = 0; g_cursor[i] = 0; }
}

// ---------------- router (exact fp32; one warp per token) ----------------
__global__ void router_kernel(const float* __restrict__ x,
                              const float* __restrict__ rw, int T) {
    int warp = (blockIdx.x * blockDim.x + threadIdx.x) >> 5;
    int lane = threadIdx.x & 31;
    if (warp >= T) return;
    const float* xr = x + (size_t)warp * HIDDEN;

    float acc[NE];
#pragma unroll
    for (int e = 0; e < NE; e++) acc[e] = 0.f;

    for (int i = lane; i < HIDDEN; i += 32) {
        float xv = __ldg(xr + i);
        const float4* rp = (const float4*)(rw + (size_t)i * NE);
        float4 r0 = __ldg(rp + 0), r1 = __ldg(rp + 1);
        float4 r2 = __ldg(rp + 2), r3 = __ldg(rp + 3);
        acc[0]  += xv * r0.x; acc[1]  += xv * r0.y; acc[2]  += xv * r0.z; acc[3]  += xv * r0.w;
        acc[4]  += xv * r1.x; acc[5]  += xv * r1.y; acc[6]  += xv * r1.z; acc[7]  += xv * r1.w;
        acc[8]  += xv * r2.x; acc[9]  += xv * r2.y; acc[10] += xv * r2.z; acc[11] += xv * r2.w;
        acc[12] += xv * r3.x; acc[13] += xv * r3.y; acc[14] += xv * r3.z; acc[15] += xv * r3.w;
    }
#pragma unroll
    for (int e = 0; e < NE; e++) {
#pragma unroll
        for (int o = 16; o > 0; o >>= 1)
            acc[e] += __shfl_xor_sync(0xffffffffu, acc[e], o);
    }

    if (lane == 0) {
        float mx = acc[0];
#pragma unroll
        for (int e = 1; e < NE; e++) mx = fmaxf(mx, acc[e]);
        float p[NE], Z = 0.f;
#pragma unroll
        for (int e = 0; e < NE; e++) { p[e] = expf(acc[e] - mx); Z += p[e]; }
        int i1 = 0; float v1 = p[0];
#pragma unroll
        for (int e = 1; e < NE; e++) if (p[e] > v1) { v1 = p[e]; i1 = e; }
        int i2 = -1; float v2 = -1.f;
#pragma unroll
        for (int e = 0; e < NE; e++)
            if (e != i1 && p[e] > v2) { v2 = p[e]; i2 = e; }
        v1 /= Z; v2 /= Z;
        float s = v1 + v2 + 1e-9f;
        g_topk_idx[warp][0] = i1; g_topk_idx[warp][1] = i2;
        g_topk_w[warp][0] = v1 / s; g_topk_w[warp][1] = v2 / s;
        atomicAdd(&g_counts[i1], 1);
        atomicAdd(&g_counts[i2], 1);
    }
}

// ---------------- scan ----------------
__global__ void scan_kernel() {
    if (threadIdx.x == 0) {
        int off = 0;
        for (int e = 0; e < NE; e++) {
            g_off[e] = off;
            int c = g_counts[e];
            off += ((c + BT - 1) / BT) * BT;
        }
        g_off[NE] = off;
        for (int t = 0; t < N_TILES; t++) {
            int r = t * BT;
            int e = NE - 1;
            for (int j = 0; j < NE; j++)
                if (r >= g_off[j] && r < g_off[j + 1]) e = j;
            g_tile_expert[t] = e;
        }
    }
}

// ---------------- scatter ----------------
__global__ void scatter_kernel(int T) {
    int t = blockIdx.x * blockDim.x + threadIdx.x;
    if (t >= T) return;
#pragma unroll
    for (int k = 0; k < 2; k++) {
        int e = g_topk_idx[t][k];
        int pos = g_off[e] + atomicAdd(&g_cursor[e], 1);
        g_perm[pos] = t;
        g_pw[pos] = g_topk_w[t][k];
        g_token_pos[t][k] = pos;
    }
}

// =======================================================================
// Tensor-core GEMM skeleton: 256 threads / 8 warps, 128x64 block tile,
// 32x32 warp tile (warp grid 4x2), BK=32, register-prefetch pipeline.
// =======================================================================

// ---------------- unified gate+up (routed + shared experts) ----------------
// grid.x = 192 routed blocks (48 tiles x 4 col-tiles of MID_R)
//        + 256 shared blocks (2 experts x 16 row-tiles x 8 col-tiles of MID_S)
__global__ void __launch_bounds__(256, 1)
gateup_all_k(const float* __restrict__ x,
             const float* __restrict__ wg_r, const float* __restrict__ wu_r,
             const float* __restrict__ wg_s, const float* __restrict__ wu_s) {
    const int NBR = N_TILES * (MID_R / 64);   // 192
    int b = blockIdx.x;

    bool routed;
    int row0, col0, ldb;
    const float* Wg;
    const float* Wu;
    float* hbase;
    int hstride;

    if (b < NBR) {
        routed = true;
        int tile = b >> 2;
        col0 = (b & 3) * 64;
        row0 = tile * BT;
        int e = g_tile_expert[tile];
        Wg = wg_r + (size_t)e * HIDDEN * MID_R;
        Wu = wu_r + (size_t)e * HIDDEN * MID_R;
        ldb = MID_R;
        hbase = &g_Hr[0][0];
        hstride = MID_R;
    } else {
        routed = false;
        b -= NBR;
        int n = b >> 7;           // 128 blocks per shared expert
        int rem = b & 127;
        row0 = (rem >> 3) * BT;
        col0 = (rem & 7) * 64;
        Wg = wg_s + (size_t)n * HIDDEN * MID_S;
        Wu = wu_s + (size_t)n * HIDDEN * MID_S;
        ldb = MID_S;
        hbase = &g_Hs[n][0][0];
        hstride = MID_S;
    }

    __shared__ unsigned As[BT * SA];
    __shared__ unsigned Bg[32 * SB];
    __shared__ unsigned Bu[32 * SB];
    __shared__ int   s_perm[BT];
    __shared__ float s_pw[BT];

    int tid = threadIdx.x, lane = tid & 31, w = tid >> 5;
    int wr = w >> 1, wc = w & 1;

    if (routed && tid < BT) {
        s_perm[tid] = g_perm[row0 + tid];
        s_pw[tid] = g_pw[row0 + tid];
    }
    __syncthreads();

    float accg[2][4][4] = {}, accu[2][4][4] = {};
    float4 pA[4], pBg[2], pBu[2];

    // A-load indices: idx = tid + 256*i  ->  r = idx>>3 (0..127), c4 = (idx&7)<<2
    // B-load indices: idx = tid + 256*i  ->  r = idx>>4 (0..31),  c4 = (idx&15)<<2
#define LOAD_A(kk)                                                              \
    _Pragma("unroll")                                                           \
    for (int i = 0; i < 4; i++) {                                               \
        int idx = tid + 256 * i;                                                \
        int r = idx >> 3, c4 = (idx & 7) << 2;                                  \
        if (routed) {                                                           \
            int grow = s_perm[r];                                               \
            pA[i] = (grow >= 0)                                                 \
                ? *(const float4*)(x + (size_t)grow * HIDDEN + (kk) + c4)       \
                : make_float4(0.f, 0.f, 0.f, 0.f);                              \
        } else {                                                                \
            pA[i] = *(const float4*)(x + (size_t)(row0 + r) * HIDDEN + (kk) + c4); \
        }                                                                       \
    }
#define LOAD_B(kk)                                                              \
    _Pragma("unroll")                                                           \
    for (int i = 0; i < 2; i++) {                                               \
        int idx = tid + 256 * i;                                                \
        int r = idx >> 4, c4 = (idx & 15) << 2;                                 \
        pBg[i] = *(const float4*)(Wg + (size_t)((kk) + r) * ldb + col0 + c4);   \
        pBu[i] = *(const float4*)(Wu + (size_t)((kk) + r) * ldb + col0 + c4);   \
    }

    LOAD_A(0)
    LOAD_B(0)

    for (int kk = 0; kk < HIDDEN; kk += 32) {
        // commit prefetched tile to smem
#pragma unroll
        for (int i = 0; i < 4; i++) {
            int idx = tid + 256 * i;
            int r = idx >> 3, c4 = (idx & 7) << 2;
            cvst4(&As[r * SA + c4], pA[i]);
        }
#pragma unroll
        for (int i = 0; i < 2; i++) {
            int idx = tid + 256 * i;
            int r = idx >> 4, c4 = (idx & 15) << 2;
            cvst4(&Bg[r * SB + c4], pBg[i]);
            cvst4(&Bu[r * SB + c4], pBu[i]);
        }
        __syncthreads();

        if (kk + 32 < HIDDEN) {   // prefetch next tile (latency hidden by MMAs)
            LOAD_A(kk + 32)
            LOAD_B(kk + 32)
        }

#pragma unroll
        for (int ks = 0; ks < 4; ks++) {
            int k0 = ks * 8;
            unsigned a[2][4];
#pragma unroll
            for (int rt = 0; rt < 2; rt++) {
                const unsigned* p = &As[(wr * 32 + rt * 16 + (lane >> 2)) * SA + k0 + (lane & 3)];
                a[rt][0] = p[0]; a[rt][1] = p[8 * SA]; a[rt][2] = p[4]; a[rt][3] = p[8 * SA + 4];
            }
            unsigned bg[4][2], bu[4][2];
#pragma unroll
            for (int ct = 0; ct < 4; ct++) {
                int ncol = wc * 32 + ct * 8 + (lane >> 2);
                const unsigned* pg = &Bg[(k0 + (lane & 3)) * SB + ncol];
                bg[ct][0] = pg[0]; bg[ct][1] = pg[4 * SB];
                const unsigned* pu = &Bu[(k0 + (lane & 3)) * SB + ncol];
                bu[ct][0] = pu[0]; bu[ct][1] = pu[4 * SB];
            }
#pragma unroll
            for (int rt = 0; rt < 2; rt++)
#pragma unroll
                for (int ct = 0; ct < 4; ct++) {
                    mma8(accg[rt][ct], a[rt], bg[ct]);
                    mma8(accu[rt][ct], a[rt], bu[ct]);
                }
        }
        __syncthreads();
    }
#undef LOAD_A
#undef LOAD_B

#pragma unroll
    for (int rt = 0; rt < 2; rt++) {
        int lr = wr * 32 + rt * 16 + (lane >> 2);
        float w0 = routed ? s_pw[lr] : 1.f;
        float w1 = routed ? s_pw[lr + 8] : 1.f;
#pragma unroll
        for (int ct = 0; ct < 4; ct++) {
            int c = col0 + wc * 32 + ct * 8 + 2 * (lane & 3);
            float* gg = accg[rt][ct];
            float* uu = accu[rt][ct];
            float2 h0 = make_float2(silu(gg[0]) * uu[0] * w0, silu(gg[1]) * uu[1] * w0);
            float2 h1 = make_float2(silu(gg[2]) * uu[2] * w1, silu(gg[3]) * uu[3] * w1);
            *(float2*)(hbase + (size_t)(row0 + lr) * hstride + c) = h0;
            *(float2*)(hbase + (size_t)(row0 + lr + 8) * hstride + c) = h1;
        }
    }
}

// ---------------- routed down-proj -> g_Y ----------------
__global__ void __launch_bounds__(256)
down_routed_k(const float* __restrict__ wd_r) {
    int tile = blockIdx.y;
    int row0 = tile * BT;
    int col0 = blockIdx.x * 64;
    int e = g_tile_expert[tile];
    const float* Wd = wd_r + (size_t)e * MID_R * HIDDEN;

    __shared__ unsigned As[BT * SA];
    __shared__ unsigned Bs[32 * SB];

    int tid = threadIdx.x, lane = tid & 31, w = tid >> 5;
    int wr = w >> 1, wc = w & 1;

    float acc[2][4][4] = {};
    float4 pA[4], pB[2];

#define LOAD_A(kk)                                                              \
    _Pragma("unroll")                                                           \
    for (int i = 0; i < 4; i++) {                                               \
        int idx = tid + 256 * i;                                                \
        int r = idx >> 3, c4 = (idx & 7) << 2;                                  \
        pA[i] = *(const float4*)&g_Hr[row0 + r][(kk) + c4];                     \
    }
#define LOAD_B(kk)                                                              \
    _Pragma("unroll")                                                           \
    for (int i = 0; i < 2; i++) {                                               \
        int idx = tid + 256 * i;                                                \
        int r = idx >> 4, c4 = (idx & 15) << 2;                                 \
        pB[i] = *(const float4*)(Wd + (size_t)((kk) + r) * HIDDEN + col0 + c4); \
    }

    LOAD_A(0)
    LOAD_B(0)

    for (int kk = 0; kk < MID_R; kk += 32) {
#pragma unroll
        for (int i = 0; i < 4; i++) {
            int idx = tid + 256 * i;
            int r = idx >> 3, c4 = (idx & 7) << 2;
            cvst4(&As[r * SA + c4], pA[i]);
        }
#pragma unroll
        for (int i = 0; i < 2; i++) {
            int idx = tid + 256 * i;
            int r = idx >> 4, c4 = (idx & 15) << 2;
            cvst4(&Bs[r * SB + c4], pB[i]);
        }
        __syncthreads();

        if (kk + 32 < MID_R) {
            LOAD_A(kk + 32)
            LOAD_B(kk + 32)
        }

#pragma unroll
        for (int ks = 0; ks < 4; ks++) {
            int k0 = ks * 8;
            unsigned a[2][4];
#pragma unroll
            for (int rt = 0; rt < 2; rt++) {
                const unsigned* p = &As[(wr * 32 + rt * 16 + (lane >> 2)) * SA + k0 + (lane & 3)];
                a[rt][0] = p[0]; a[rt][1] = p[8 * SA]; a[rt][2] = p[4]; a[rt][3] = p[8 * SA + 4];
            }
            unsigned bfr[4][2];
#pragma unroll
            for (int ct = 0; ct < 4; ct++) {
                int ncol = wc * 32 + ct * 8 + (lane >> 2);
                const unsigned* pb = &Bs[(k0 + (lane & 3)) * SB + ncol];
                bfr[ct][0] = pb[0]; bfr[ct][1] = pb[4 * SB];
            }
#pragma unroll
            for (int rt = 0; rt < 2; rt++)
#pragma unroll
                for (int ct = 0; ct < 4; ct++)
                    mma8(acc[rt][ct], a[rt], bfr[ct]);
        }
        __syncthreads();
    }
#undef LOAD_A
#undef LOAD_B

#pragma unroll
    for (int rt = 0; rt < 2; rt++) {
        int r0 = row0 + wr * 32 + rt * 16 + (lane >> 2);
#pragma unroll
        for (int ct = 0; ct < 4; ct++) {
            int c = col0 + wc * 32 + ct * 8 + 2 * (lane & 3);
            *(float2*)&g_Y[r0][c] = make_float2(acc[rt][ct][0], acc[rt][ct][1]);
            *(float2*)&g_Y[r0 + 8][c] = make_float2(acc[rt][ct][2], acc[rt][ct][3]);
        }
    }
}

// ---------------- shared down-proj + routed combine -> out ----------------
__global__ void __launch_bounds__(256)
down_shared_k(const float* __restrict__ wd_s, float* __restrict__ out) {
    int row0 = blockIdx.y * BT;
    int col0 = blockIdx.x * 64;

    __shared__ unsigned As[BT * SA];
    __shared__ unsigned Bs[32 * SB];
    __shared__ int s_p0[BT], s_p1[BT];

    int tid = threadIdx.x, lane = tid & 31, w = tid >> 5;
    int wr = w >> 1, wc = w & 1;
    if (tid < BT) {
        s_p0[tid] = g_token_pos[row0 + tid][0];
        s_p1[tid] = g_token_pos[row0 + tid][1];
    }

    float acc[2][4][4] = {};
    float4 pA[4], pB[2];

#define LOAD_A(n, kk)                                                           \
    _Pragma("unroll")                                                           \
    for (int i = 0; i < 4; i++) {                                               \
        int idx = tid + 256 * i;                                                \
        int r = idx >> 3, c4 = (idx & 7) << 2;                                  \
        pA[i] = *(const float4*)&g_Hs[n][row0 + r][(kk) + c4];                  \
    }
#define LOAD_B(n, kk)                                                           \
    _Pragma("unroll")                                                           \
    for (int i = 0; i < 2; i++) {                                               \
        int idx = tid + 256 * i;                                                \
        int r = idx >> 4, c4 = (idx & 15) << 2;                                 \
        pB[i] = *(const float4*)(wd_s + (size_t)(n) * MID_S * HIDDEN            \
                                 + (size_t)((kk) + r) * HIDDEN + col0 + c4);    \
    }

    LOAD_A(0, 0)
    LOAD_B(0, 0)

    for (int it = 0; it < 2 * (MID_S / 32); it++) {   // 32 iters over both experts
        __syncthreads();   // also covers s_p0/s_p1 init on first pass
#pragma unroll
        for (int i = 0; i < 4; i++) {
            int idx = tid + 256 * i;
            int r = idx >> 3, c4 = (idx & 7) << 2;
            cvst4(&As[r * SA + c4], pA[i]);
        }
#pragma unroll
        for (int i = 0; i < 2; i++) {
            int idx = tid + 256 * i;
            int r = idx >> 4, c4 = (idx & 15) << 2;
            cvst4(&Bs[r * SB + c4], pB[i]);
        }
        __syncthreads();

        if (it + 1 < 2 * (MID_S / 32)) {
            int nxt = it + 1;
            int n2 = nxt / (MID_S / 32);
            int kk2 = (nxt % (MID_S / 32)) * 32;
            LOAD_A(n2, kk2)
            LOAD_B(n2, kk2)
        }

#pragma unroll
        for (int ks = 0; ks < 4; ks++) {
            int k0 = ks * 8;
            unsigned a[2][4];
#pragma unroll
            for (int rt = 0; rt < 2; rt++) {
                const unsigned* p = &As[(wr * 32 + rt * 16 + (lane >> 2)) * SA + k0 + (lane & 3)];
                a[rt][0] = p[0]; a[rt][1] = p[8 * SA]; a[rt][2] = p[4]; a[rt][3] = p[8 * SA + 4];
            }
            unsigned bfr[4][2];
#pragma unroll
            for (int ct = 0; ct < 4; ct++) {
                int ncol = wc * 32 + ct * 8 + (lane >> 2);
                const unsigned* pb = &Bs[(k0 + (lane & 3)) * SB + ncol];
                bfr[ct][0] = pb[0]; bfr[ct][1] = pb[4 * SB];
            }
#pragma unroll
            for (int rt = 0; rt < 2; rt++)
#pragma unroll
                for (int ct = 0; ct < 4; ct++)
                    mma8(acc[rt][ct], a[rt], bfr[ct]);
        }
    }
#undef LOAD_A
#undef LOAD_B

    __syncthreads();
#pragma unroll
    for (int rt = 0; rt < 2; rt++) {
        int lr = wr * 32 + rt * 16 + (lane >> 2);
        int r0 = row0 + lr;
        int p0a = s_p0[lr], p1a = s_p1[lr];
        int p0b = s_p0[lr + 8], p1b = s_p1[lr + 8];
#pragma unroll
        for (int ct = 0; ct < 4; ct++) {
            int c = col0 + wc * 32 + ct * 8 + 2 * (lane & 3);
            float2 ya = *(const float2*)&g_Y[p0a][c];
            float2 yb = *(const float2*)&g_Y[p1a][c];
            *(float2*)(out + (size_t)r0 * HIDDEN + c) =
                make_float2(acc[rt][ct][0] + ya.x + yb.x,
                            acc[rt][ct][1] + ya.y + yb.y);
            float2 yc = *(const float2*)&g_Y[p0b][c];
            float2 yd = *(const float2*)&g_Y[p1b][c];
            *(float2*)(out + (size_t)(r0 + 8) * HIDDEN + c) =
                make_float2(acc[rt][ct][2] + yc.x + yd.x,
                            acc[rt][ct][3] + yc.y + yd.y);
        }
    }
}

// ---------------- launch ----------------
extern "C" void kernel_launch(void* const* d_in, const int* in_sizes, int n_in,
                              void* d_out, int out_size) {
    const float* x    = (const float*)d_in[0];
    const float* rw   = (const float*)d_in[1];
    const float* wg_r = (const float*)d_in[2];
    const float* wu_r = (const float*)d_in[3];
    const float* wd_r = (const float*)d_in[4];
    const float* wg_s = (const float*)d_in[5];
    const float* wu_s = (const float*)d_in[6];
    const float* wd_s = (const float*)d_in[7];
    float* out = (float*)d_out;

    int T = in_sizes[0] / HIDDEN;
    if (T > MAX_T || T % BT != 0) return;

    init_kernel<<<(PADDED_CAP + 255) / 256, 256>>>();
    router_kernel<<<(T + 7) / 8, 256>>>(x, rw, T);
    scan_kernel<<<1, 32>>>();
    scatter_kernel<<<(T + 255) / 256, 256>>>(T);

    int nb_gateup = N_TILES * (MID_R / 64)                 // 192 routed
                  + NS * (T / BT) * (MID_S / 64);          // 256 shared
    gateup_all_k<<<nb_gateup, 256>>>(x, wg_r, wu_r, wg_s, wu_s);

    dim3 gdr(HIDDEN / 64, N_TILES);
    down_routed_k<<<gdr, 256>>>(wd_r);

    dim3 gds(HIDDEN / 64, T / BT);
    down_shared_k<<<gds, 256>>>(wd_s, out);
}

// round 6
// speedup vs baseline: 2.5785x; 1.2304x over previous
#include <cuda_runtime.h>
#include <cuda_fp16.h>
#include <math.h>
#include <stdint.h>

#define HIDDEN 1024
#define NE 16
#define NS 2
#define MID_R 256
#define MID_S 512
#define MAX_T 2048
#define BT 128                              // expert segment alignment = GEMM row tile
#define PADDED_CAP (MAX_T * 2 + NE * BT)    // 6144
#define N_TILES (PADDED_CAP / BT)           // 48

#define SAH 40   // A smem stride (halves): bank=(20m+q)%32 conflict-free
#define SBH 40   // B smem stride (halves), B stored [n][k]

// ---------------- device scratch ----------------
__device__ float g_Hs[NS][MAX_T][MID_S];
__device__ float g_Hr[PADDED_CAP][MID_R];
__device__ float g_Y[PADDED_CAP][HIDDEN];
__device__ int   g_topk_idx[MAX_T][2];
__device__ float g_topk_w[MAX_T][2];
__device__ int   g_counts[NE];
__device__ int   g_off[NE + 1];
__device__ int   g_cursor[NE];
__device__ int   g_perm[PADDED_CAP];
__device__ float g_pw[PADDED_CAP];
__device__ int   g_token_pos[MAX_T][2];
__device__ int   g_tile_expert[N_TILES];

// ---------------- helpers ----------------
__device__ __forceinline__ uint32_t h2pack(float a, float b) {
    __half2 h = __floats2half2_rn(a, b);
    return *(uint32_t*)&h;
}

__device__ __forceinline__ void mma16(float* c, const unsigned* a, const unsigned* b) {
    asm volatile(
        "mma.sync.aligned.m16n8k16.row.col.f32.f16.f16.f32 "
        "{%0,%1,%2,%3},{%4,%5,%6,%7},{%8,%9},{%0,%1,%2,%3};"
        : "+f"(c[0]), "+f"(c[1]), "+f"(c[2]), "+f"(c[3])
        : "r"(a[0]), "r"(a[1]), "r"(a[2]), "r"(a[3]), "r"(b[0]), "r"(b[1]));
}

__device__ __forceinline__ float silu(float g) { return g / (1.f + __expf(-g)); }

// ---------------- init ----------------
__global__ void init_kernel() {
    int i = blockIdx.x * blockDim.x + threadIdx.x;
    if (i < PADDED_CAP) { g_perm[i] = -1; g_pw[i] = 0.f; }
    if (i < NE) { g_counts[i] = 0; g_cursor[i] = 0; }
}

// ---------------- router (exact fp32; one warp per token) ----------------
__global__ void router_kernel(const float* __restrict__ x,
                              const float* __restrict__ rw, int T) {
    int warp = (blockIdx.x * blockDim.x + threadIdx.x) >> 5;
    int lane = threadIdx.x & 31;
    if (warp >= T) return;
    const float* xr = x + (size_t)warp * HIDDEN;

    float acc[NE];
#pragma unroll
    for (int e = 0; e < NE; e++) acc[e] = 0.f;

    for (int i = lane; i < HIDDEN; i += 32) {
        float xv = __ldg(xr + i);
        const float4* rp = (const float4*)(rw + (size_t)i * NE);
        float4 r0 = __ldg(rp + 0), r1 = __ldg(rp + 1);
        float4 r2 = __ldg(rp + 2), r3 = __ldg(rp + 3);
        acc[0]  += xv * r0.x; acc[1]  += xv * r0.y; acc[2]  += xv * r0.z; acc[3]  += xv * r0.w;
        acc[4]  += xv * r1.x; acc[5]  += xv * r1.y; acc[6]  += xv * r1.z; acc[7]  += xv * r1.w;
        acc[8]  += xv * r2.x; acc[9]  += xv * r2.y; acc[10] += xv * r2.z; acc[11] += xv * r2.w;
        acc[12] += xv * r3.x; acc[13] += xv * r3.y; acc[14] += xv * r3.z; acc[15] += xv * r3.w;
    }
#pragma unroll
    for (int e = 0; e < NE; e++) {
#pragma unroll
        for (int o = 16; o > 0; o >>= 1)
            acc[e] += __shfl_xor_sync(0xffffffffu, acc[e], o);
    }

    if (lane == 0) {
        float mx = acc[0];
#pragma unroll
        for (int e = 1; e < NE; e++) mx = fmaxf(mx, acc[e]);
        float p[NE], Z = 0.f;
#pragma unroll
        for (int e = 0; e < NE; e++) { p[e] = expf(acc[e] - mx); Z += p[e]; }
        int i1 = 0; float v1 = p[0];
#pragma unroll
        for (int e = 1; e < NE; e++) if (p[e] > v1) { v1 = p[e]; i1 = e; }
        int i2 = -1; float v2 = -1.f;
#pragma unroll
        for (int e = 0; e < NE; e++)
            if (e != i1 && p[e] > v2) { v2 = p[e]; i2 = e; }
        v1 /= Z; v2 /= Z;
        float s = v1 + v2 + 1e-9f;
        g_topk_idx[warp][0] = i1; g_topk_idx[warp][1] = i2;
        g_topk_w[warp][0] = v1 / s; g_topk_w[warp][1] = v2 / s;
        atomicAdd(&g_counts[i1], 1);
        atomicAdd(&g_counts[i2], 1);
    }
}

// ---------------- scan ----------------
__global__ void scan_kernel() {
    if (threadIdx.x == 0) {
        int off = 0;
        for (int e = 0; e < NE; e++) {
            g_off[e] = off;
            int c = g_counts[e];
            off += ((c + BT - 1) / BT) * BT;
        }
        g_off[NE] = off;
        for (int t = 0; t < N_TILES; t++) {
            int r = t * BT;
            int e = NE - 1;
            for (int j = 0; j < NE; j++)
                if (r >= g_off[j] && r < g_off[j + 1]) e = j;
            g_tile_expert[t] = e;
        }
    }
}

// ---------------- scatter ----------------
__global__ void scatter_kernel(int T) {
    int t = blockIdx.x * blockDim.x + threadIdx.x;
    if (t >= T) return;
#pragma unroll
    for (int k = 0; k < 2; k++) {
        int e = g_topk_idx[t][k];
        int pos = g_off[e] + atomicAdd(&g_cursor[e], 1);
        g_perm[pos] = t;
        g_pw[pos] = g_topk_w[t][k];
        g_token_pos[t][k] = pos;
    }
}

// =======================================================================
// fp16 tensor-core GEMMs: 256 threads / 8 warps, 128x64 block tile,
// 32x32 warp tile (warp grid 4x2), BK=32, mma.sync.m16n8k16 f16->f32,
// register-prefetch pipeline. A smem [m][k] (stride SAH), B smem
// TRANSPOSED [n][k] (stride SBH) so B fragments are contiguous half2.
// =======================================================================

// A fragment loads for warp-row wr, ks in {0,1}:
//   row = wr*32 + rt*16 + (lane>>2), q2 = 2*(lane&3), k0 = ks*16
//   a0=[row][k0+q2] a1=[row+8][k0+q2] a2=[row][k0+q2+8] a3=[row+8][k0+q2+8]
// B fragment: col = wc*32+ct*8+(lane>>2): b0=[col][k0+q2], b1=[col][k0+q2+8]

// ---------------- unified gate+up (routed + shared experts) ----------------
__global__ void __launch_bounds__(256)
gateup_all_k(const float* __restrict__ x,
             const float* __restrict__ wg_r, const float* __restrict__ wu_r,
             const float* __restrict__ wg_s, const float* __restrict__ wu_s) {
    const int NBR = N_TILES * (MID_R / 64);   // 192
    int b = blockIdx.x;

    bool routed;
    int row0, col0, ldb;
    const float* Wg;
    const float* Wu;
    float* hbase;
    int hstride;

    if (b < NBR) {
        routed = true;
        int tile = b >> 2;
        col0 = (b & 3) * 64;
        row0 = tile * BT;
        if (row0 >= g_off[NE]) return;     // fully-padded tail tile: skip
        int e = g_tile_expert[tile];
        Wg = wg_r + (size_t)e * HIDDEN * MID_R;
        Wu = wu_r + (size_t)e * HIDDEN * MID_R;
        ldb = MID_R;
        hbase = &g_Hr[0][0];
        hstride = MID_R;
    } else {
        routed = false;
        b -= NBR;
        int n = b >> 7;           // 128 blocks per shared expert
        int rem = b & 127;
        row0 = (rem >> 3) * BT;
        col0 = (rem & 7) * 64;
        Wg = wg_s + (size_t)n * HIDDEN * MID_S;
        Wu = wu_s + (size_t)n * HIDDEN * MID_S;
        ldb = MID_S;
        hbase = &g_Hs[n][0][0];
        hstride = MID_S;
    }

    __shared__ __half As[BT * SAH];
    __shared__ __half Bg[64 * SBH];
    __shared__ __half Bu[64 * SBH];
    __shared__ int   s_perm[BT];
    __shared__ float s_pw[BT];

    int tid = threadIdx.x, lane = tid & 31, w = tid >> 5;
    int wr = w >> 1, wc = w & 1;
    int q2 = 2 * (lane & 3);

    if (routed && tid < BT) {
        s_perm[tid] = g_perm[row0 + tid];
        s_pw[tid] = g_pw[row0 + tid];
    }
    __syncthreads();

    float accg[2][4][4] = {}, accu[2][4][4] = {};
    float4 pA[4], pBg[2], pBu[2];

#define LOAD_A(kk)                                                              \
    _Pragma("unroll")                                                           \
    for (int i = 0; i < 4; i++) {                                               \
        int idx = tid + 256 * i;                                                \
        int r = idx >> 3, c4 = (idx & 7) << 2;                                  \
        if (routed) {                                                           \
            int grow = s_perm[r];                                               \
            pA[i] = (grow >= 0)                                                 \
                ? *(const float4*)(x + (size_t)grow * HIDDEN + (kk) + c4)       \
                : make_float4(0.f, 0.f, 0.f, 0.f);                              \
        } else {                                                                \
            pA[i] = *(const float4*)(x + (size_t)(row0 + r) * HIDDEN + (kk) + c4); \
        }                                                                       \
    }
#define LOAD_B(kk)                                                              \
    _Pragma("unroll")                                                           \
    for (int i = 0; i < 2; i++) {                                               \
        int idx = tid + 256 * i;                                                \
        int r = idx >> 4, c4 = (idx & 15) << 2;                                 \
        pBg[i] = *(const float4*)(Wg + (size_t)((kk) + r) * ldb + col0 + c4);   \
        pBu[i] = *(const float4*)(Wu + (size_t)((kk) + r) * ldb + col0 + c4);   \
    }

    LOAD_A(0)
    LOAD_B(0)

    for (int kk = 0; kk < HIDDEN; kk += 32) {
        // commit prefetched tile to smem (convert to fp16)
#pragma unroll
        for (int i = 0; i < 4; i++) {
            int idx = tid + 256 * i;
            int r = idx >> 3, c4 = (idx & 7) << 2;
            uint2 u;
            u.x = h2pack(pA[i].x, pA[i].y);
            u.y = h2pack(pA[i].z, pA[i].w);
            *(uint2*)&As[r * SAH + c4] = u;
        }
#pragma unroll
        for (int i = 0; i < 2; i++) {
            int idx = tid + 256 * i;
            int k = idx >> 4, n4 = (idx & 15) << 2;
            Bg[(n4 + 0) * SBH + k] = __float2half_rn(pBg[i].x);
            Bg[(n4 + 1) * SBH + k] = __float2half_rn(pBg[i].y);
            Bg[(n4 + 2) * SBH + k] = __float2half_rn(pBg[i].z);
            Bg[(n4 + 3) * SBH + k] = __float2half_rn(pBg[i].w);
            Bu[(n4 + 0) * SBH + k] = __float2half_rn(pBu[i].x);
            Bu[(n4 + 1) * SBH + k] = __float2half_rn(pBu[i].y);
            Bu[(n4 + 2) * SBH + k] = __float2half_rn(pBu[i].z);
            Bu[(n4 + 3) * SBH + k] = __float2half_rn(pBu[i].w);
        }
        __syncthreads();

        if (kk + 32 < HIDDEN) {   // prefetch next tile
            LOAD_A(kk + 32)
            LOAD_B(kk + 32)
        }

#pragma unroll
        for (int ks = 0; ks < 2; ks++) {
            int k0 = ks * 16;
            unsigned a[2][4];
#pragma unroll
            for (int rt = 0; rt < 2; rt++) {
                const __half* p = &As[(wr * 32 + rt * 16 + (lane >> 2)) * SAH + k0 + q2];
                a[rt][0] = *(const unsigned*)p;
                a[rt][1] = *(const unsigned*)(p + 8 * SAH);
                a[rt][2] = *(const unsigned*)(p + 8);
                a[rt][3] = *(const unsigned*)(p + 8 * SAH + 8);
            }
            unsigned bg[4][2], bu[4][2];
#pragma unroll
            for (int ct = 0; ct < 4; ct++) {
                int col = wc * 32 + ct * 8 + (lane >> 2);
                const __half* pg = &Bg[col * SBH + k0 + q2];
                bg[ct][0] = *(const unsigned*)pg;
                bg[ct][1] = *(const unsigned*)(pg + 8);
                const __half* pu = &Bu[col * SBH + k0 + q2];
                bu[ct][0] = *(const unsigned*)pu;
                bu[ct][1] = *(const unsigned*)(pu + 8);
            }
#pragma unroll
            for (int rt = 0; rt < 2; rt++)
#pragma unroll
                for (int ct = 0; ct < 4; ct++) {
                    mma16(accg[rt][ct], a[rt], bg[ct]);
                    mma16(accu[rt][ct], a[rt], bu[ct]);
                }
        }
        __syncthreads();
    }
#undef LOAD_A
#undef LOAD_B

#pragma unroll
    for (int rt = 0; rt < 2; rt++) {
        int lr = wr * 32 + rt * 16 + (lane >> 2);
        float w0 = routed ? s_pw[lr] : 1.f;
        float w1 = routed ? s_pw[lr + 8] : 1.f;
#pragma unroll
        for (int ct = 0; ct < 4; ct++) {
            int c = col0 + wc * 32 + ct * 8 + q2;
            float* gg = accg[rt][ct];
            float* uu = accu[rt][ct];
            float2 h0 = make_float2(silu(gg[0]) * uu[0] * w0, silu(gg[1]) * uu[1] * w0);
            float2 h1 = make_float2(silu(gg[2]) * uu[2] * w1, silu(gg[3]) * uu[3] * w1);
            *(float2*)(hbase + (size_t)(row0 + lr) * hstride + c) = h0;
            *(float2*)(hbase + (size_t)(row0 + lr + 8) * hstride + c) = h1;
        }
    }
}

// ---------------- routed down-proj -> g_Y ----------------
__global__ void __launch_bounds__(256)
down_routed_k(const float* __restrict__ wd_r) {
    int tile = blockIdx.y;
    int row0 = tile * BT;
    if (row0 >= g_off[NE]) return;     // fully-padded tail tile: skip
    int col0 = blockIdx.x * 64;
    int e = g_tile_expert[tile];
    const float* Wd = wd_r + (size_t)e * MID_R * HIDDEN;

    __shared__ __half As[BT * SAH];
    __shared__ __half Bs[64 * SBH];

    int tid = threadIdx.x, lane = tid & 31, w = tid >> 5;
    int wr = w >> 1, wc = w & 1;
    int q2 = 2 * (lane & 3);

    float acc[2][4][4] = {};
    float4 pA[4], pB[2];

#define LOAD_A(kk)                                                              \
    _Pragma("unroll")                                                           \
    for (int i = 0; i < 4; i++) {                                               \
        int idx = tid + 256 * i;                                                \
        int r = idx >> 3, c4 = (idx & 7) << 2;                                  \
        pA[i] = *(const float4*)&g_Hr[row0 + r][(kk) + c4];                     \
    }
#define LOAD_B(kk)                                                              \
    _Pragma("unroll")                                                           \
    for (int i = 0; i < 2; i++) {                                               \
        int idx = tid + 256 * i;                                                \
        int r = idx >> 4, c4 = (idx & 15) << 2;                                 \
        pB[i] = *(const float4*)(Wd + (size_t)((kk) + r) * HIDDEN + col0 + c4); \
    }

    LOAD_A(0)
    LOAD_B(0)

    for (int kk = 0; kk < MID_R; kk += 32) {
#pragma unroll
        for (int i = 0; i < 4; i++) {
            int idx = tid + 256 * i;
            int r = idx >> 3, c4 = (idx & 7) << 2;
            uint2 u;
            u.x = h2pack(pA[i].x, pA[i].y);
            u.y = h2pack(pA[i].z, pA[i].w);
            *(uint2*)&As[r * SAH + c4] = u;
        }
#pragma unroll
        for (int i = 0; i < 2; i++) {
            int idx = tid + 256 * i;
            int k = idx >> 4, n4 = (idx & 15) << 2;
            Bs[(n4 + 0) * SBH + k] = __float2half_rn(pB[i].x);
            Bs[(n4 + 1) * SBH + k] = __float2half_rn(pB[i].y);
            Bs[(n4 + 2) * SBH + k] = __float2half_rn(pB[i].z);
            Bs[(n4 + 3) * SBH + k] = __float2half_rn(pB[i].w);
        }
        __syncthreads();

        if (kk + 32 < MID_R) {
            LOAD_A(kk + 32)
            LOAD_B(kk + 32)
        }

#pragma unroll
        for (int ks = 0; ks < 2; ks++) {
            int k0 = ks * 16;
            unsigned a[2][4];
#pragma unroll
            for (int rt = 0; rt < 2; rt++) {
                const __half* p = &As[(wr * 32 + rt * 16 + (lane >> 2)) * SAH + k0 + q2];
                a[rt][0] = *(const unsigned*)p;
                a[rt][1] = *(const unsigned*)(p + 8 * SAH);
                a[rt][2] = *(const unsigned*)(p + 8);
                a[rt][3] = *(const unsigned*)(p + 8 * SAH + 8);
            }
            unsigned bfr[4][2];
#pragma unroll
            for (int ct = 0; ct < 4; ct++) {
                int col = wc * 32 + ct * 8 + (lane >> 2);
                const __half* pb = &Bs[col * SBH + k0 + q2];
                bfr[ct][0] = *(const unsigned*)pb;
                bfr[ct][1] = *(const unsigned*)(pb + 8);
            }
#pragma unroll
            for (int rt = 0; rt < 2; rt++)
#pragma unroll
                for (int ct = 0; ct < 4; ct++)
                    mma16(acc[rt][ct], a[rt], bfr[ct]);
        }
        __syncthreads();
    }
#undef LOAD_A
#undef LOAD_B

#pragma unroll
    for (int rt = 0; rt < 2; rt++) {
        int r0 = row0 + wr * 32 + rt * 16 + (lane >> 2);
#pragma unroll
        for (int ct = 0; ct < 4; ct++) {
            int c = col0 + wc * 32 + ct * 8 + q2;
            *(float2*)&g_Y[r0][c] = make_float2(acc[rt][ct][0], acc[rt][ct][1]);
            *(float2*)&g_Y[r0 + 8][c] = make_float2(acc[rt][ct][2], acc[rt][ct][3]);
        }
    }
}

// ---------------- shared down-proj + routed combine -> out ----------------
__global__ void __launch_bounds__(256)
down_shared_k(const float* __restrict__ wd_s, float* __restrict__ out) {
    int row0 = blockIdx.y * BT;
    int col0 = blockIdx.x * 64;

    __shared__ __half As[BT * SAH];
    __shared__ __half Bs[64 * SBH];
    __shared__ int s_p0[BT], s_p1[BT];

    int tid = threadIdx.x, lane = tid & 31, w = tid >> 5;
    int wr = w >> 1, wc = w & 1;
    int q2 = 2 * (lane & 3);
    if (tid < BT) {
        s_p0[tid] = g_token_pos[row0 + tid][0];
        s_p1[tid] = g_token_pos[row0 + tid][1];
    }

    float acc[2][4][4] = {};
    float4 pA[4], pB[2];

#define LOAD_A(n, kk)                                                           \
    _Pragma("unroll")                                                           \
    for (int i = 0; i < 4; i++) {                                               \
        int idx = tid + 256 * i;                                                \
        int r = idx >> 3, c4 = (idx & 7) << 2;                                  \
        pA[i] = *(const float4*)&g_Hs[n][row0 + r][(kk) + c4];                  \
    }
#define LOAD_B(n, kk)                                                           \
    _Pragma("unroll")                                                           \
    for (int i = 0; i < 2; i++) {                                               \
        int idx = tid + 256 * i;                                                \
        int r = idx >> 4, c4 = (idx & 15) << 2;                                 \
        pB[i] = *(const float4*)(wd_s + (size_t)(n) * MID_S * HIDDEN            \
                                 + (size_t)((kk) + r) * HIDDEN + col0 + c4);    \
    }

    LOAD_A(0, 0)
    LOAD_B(0, 0)

    const int CPE = MID_S / 32;              // 16 chunks per expert
    for (int it = 0; it < NS * CPE; it++) {  // 32 iters over both experts
        __syncthreads();   // also covers s_p0/s_p1 init on first pass
#pragma unroll
        for (int i = 0; i < 4; i++) {
            int idx = tid + 256 * i;
            int r = idx >> 3, c4 = (idx & 7) << 2;
            uint2 u;
            u.x = h2pack(pA[i].x, pA[i].y);
            u.y = h2pack(pA[i].z, pA[i].w);
            *(uint2*)&As[r * SAH + c4] = u;
        }
#pragma unroll
        for (int i = 0; i < 2; i++) {
            int idx = tid + 256 * i;
            int k = idx >> 4, n4 = (idx & 15) << 2;
            Bs[(n4 + 0) * SBH + k] = __float2half_rn(pB[i].x);
            Bs[(n4 + 1) * SBH + k] = __float2half_rn(pB[i].y);
            Bs[(n4 + 2) * SBH + k] = __float2half_rn(pB[i].z);
            Bs[(n4 + 3) * SBH + k] = __float2half_rn(pB[i].w);
        }
        __syncthreads();

        if (it + 1 < NS * CPE) {
            int nxt = it + 1;
            int n2 = nxt / CPE;
            int kk2 = (nxt % CPE) * 32;
            LOAD_A(n2, kk2)
            LOAD_B(n2, kk2)
        }

#pragma unroll
        for (int ks = 0; ks < 2; ks++) {
            int k0 = ks * 16;
            unsigned a[2][4];
#pragma unroll
            for (int rt = 0; rt < 2; rt++) {
                const __half* p = &As[(wr * 32 + rt * 16 + (lane >> 2)) * SAH + k0 + q2];
                a[rt][0] = *(const unsigned*)p;
                a[rt][1] = *(const unsigned*)(p + 8 * SAH);
                a[rt][2] = *(const unsigned*)(p + 8);
                a[rt][3] = *(const unsigned*)(p + 8 * SAH + 8);
            }
            unsigned bfr[4][2];
#pragma unroll
            for (int ct = 0; ct < 4; ct++) {
                int col = wc * 32 + ct * 8 + (lane >> 2);
                const __half* pb = &Bs[col * SBH + k0 + q2];
                bfr[ct][0] = *(const unsigned*)pb;
                bfr[ct][1] = *(const unsigned*)(pb + 8);
            }
#pragma unroll
            for (int rt = 0; rt < 2; rt++)
#pragma unroll
                for (int ct = 0; ct < 4; ct++)
                    mma16(acc[rt][ct], a[rt], bfr[ct]);
        }
    }
#undef LOAD_A
#undef LOAD_B

    __syncthreads();
#pragma unroll
    for (int rt = 0; rt < 2; rt++) {
        int lr = wr * 32 + rt * 16 + (lane >> 2);
        int r0 = row0 + lr;
        int p0a = s_p0[lr], p1a = s_p1[lr];
        int p0b = s_p0[lr + 8], p1b = s_p1[lr + 8];
#pragma unroll
        for (int ct = 0; ct < 4; ct++) {
            int c = col0 + wc * 32 + ct * 8 + q2;
            float2 ya = *(const float2*)&g_Y[p0a][c];
            float2 yb = *(const float2*)&g_Y[p1a][c];
            *(float2*)(out + (size_t)r0 * HIDDEN + c) =
                make_float2(acc[rt][ct][0] + ya.x + yb.x,
                            acc[rt][ct][1] + ya.y + yb.y);
            float2 yc = *(const float2*)&g_Y[p0b][c];
            float2 yd = *(const float2*)&g_Y[p1b][c];
            *(float2*)(out + (size_t)(r0 + 8) * HIDDEN + c) =
                make_float2(acc[rt][ct][2] + yc.x + yd.x,
                            acc[rt][ct][3] + yc.y + yd.y);
        }
    }
}

// ---------------- launch ----------------
extern "C" void kernel_launch(void* const* d_in, const int* in_sizes, int n_in,
                              void* d_out, int out_size) {
    const float* x    = (const float*)d_in[0];
    const float* rw   = (const float*)d_in[1];
    const float* wg_r = (const float*)d_in[2];
    const float* wu_r = (const float*)d_in[3];
    const float* wd_r = (const float*)d_in[4];
    const float* wg_s = (const float*)d_in[5];
    const float* wu_s = (const float*)d_in[6];
    const float* wd_s = (const float*)d_in[7];
    float* out = (float*)d_out;

    int T = in_sizes[0] / HIDDEN;
    if (T > MAX_T || T % BT != 0) return;

    init_kernel<<<(PADDED_CAP + 255) / 256, 256>>>();
    router_kernel<<<(T + 7) / 8, 256>>>(x, rw, T);
    scan_kernel<<<1, 32>>>();
    scatter_kernel<<<(T + 255) / 256, 256>>>(T);

    int nb_gateup = N_TILES * (MID_R / 64)                 // 192 routed
                  + NS * (T / BT) * (MID_S / 64);          // 256 shared
    gateup_all_k<<<nb_gateup, 256>>>(x, wg_r, wu_r, wg_s, wu_s);

    dim3 gdr(HIDDEN / 64, N_TILES);
    down_routed_k<<<gdr, 256>>>(wd_r);

    dim3 gds(HIDDEN / 64, T / BT);
    down_shared_k<<<gds, 256>>>(wd_s, out);
}

// round 7
// speedup vs baseline: 4.1036x; 1.5914x over previous
#include <cuda_runtime.h>
#include <cuda_fp16.h>
#include <math.h>
#include <stdint.h>

#define HIDDEN 1024
#define NE 16
#define NS 2
#define MID_R 256
#define MID_S 512
#define MAX_T 2048
#define BT 128
#define PADDED_CAP (MAX_T * 2 + NE * BT)    // 6144
#define N_TILES (PADDED_CAP / BT)           // 48

#define SAH 40   // A smem stride (halves); ldmatrix-conflict-free
#define SBH 40   // B smem stride (halves)

// ---------------- device scratch ----------------
__device__ __half h_x[MAX_T * HIDDEN];
__device__ __half h_wg_r[NE * MID_R * HIDDEN];   // [e][n][k]
__device__ __half h_wu_r[NE * MID_R * HIDDEN];
__device__ __half h_wd_r[NE * HIDDEN * MID_R];   // [e][n][k], k=MID_R
__device__ __half h_wg_s[NS * MID_S * HIDDEN];
__device__ __half h_wu_s[NS * MID_S * HIDDEN];
__device__ __half h_wd_s[NS * HIDDEN * MID_S];
__device__ __half h_Hr[PADDED_CAP * MID_R];
__device__ __half h_Hs[NS * MAX_T * MID_S];
__device__ float  g_Y[PADDED_CAP][HIDDEN];
__device__ int    g_topk_idx[MAX_T][2];
__device__ float  g_topk_w[MAX_T][2];
__device__ int    g_counts[NE];
__device__ int    g_off[NE + 1];
__device__ int    g_cursor[NE];
__device__ int    g_perm[PADDED_CAP];
__device__ float  g_pw[PADDED_CAP];
__device__ int    g_token_pos[MAX_T][2];
__device__ int    g_tile_expert[N_TILES];

// ---------------- helpers ----------------
__device__ __forceinline__ void mma16(float* c, const unsigned* a, const unsigned* b) {
    asm volatile(
        "mma.sync.aligned.m16n8k16.row.col.f32.f16.f16.f32 "
        "{%0,%1,%2,%3},{%4,%5,%6,%7},{%8,%9},{%0,%1,%2,%3};"
        : "+f"(c[0]), "+f"(c[1]), "+f"(c[2]), "+f"(c[3])
        : "r"(a[0]), "r"(a[1]), "r"(a[2]), "r"(a[3]), "r"(b[0]), "r"(b[1]));
}

__device__ __forceinline__ void ldsm4(unsigned* r, uint32_t a) {
    asm volatile("ldmatrix.sync.aligned.m8n8.x4.shared.b16 {%0,%1,%2,%3}, [%4];"
                 : "=r"(r[0]), "=r"(r[1]), "=r"(r[2]), "=r"(r[3]) : "r"(a));
}

__device__ __forceinline__ uint32_t smem_u32(const void* p) {
    uint32_t a;
    asm("{ .reg .u64 t; cvta.to.shared.u64 t, %1; cvt.u32.u64 %0, t; }" : "=r"(a) : "l"(p));
    return a;
}

#define CP16(d, s)      asm volatile("cp.async.ca.shared.global [%0], [%1], 16;" :: "r"(d), "l"(s))
#define CP16Z(d, s, n)  asm volatile("cp.async.ca.shared.global [%0], [%1], 16, %2;" :: "r"(d), "l"(s), "r"(n))
#define CPCOMMIT()      asm volatile("cp.async.commit_group;")
#define CPWAIT(n)       asm volatile("cp.async.wait_group %0;" :: "n"(n))

__device__ __forceinline__ float silu(float g) { return g / (1.f + __expf(-g)); }

// ---------------- init ----------------
__global__ void init_kernel() {
    int i = blockIdx.x * blockDim.x + threadIdx.x;
    if (i < PADDED_CAP) { g_perm[i] = -1; g_pw[i] = 0.f; }
    if (i < NE) { g_counts[i] = 0; g_cursor[i] = 0; }
}

// ---------------- x -> fp16 ----------------
__global__ void convert_x_k(const float* __restrict__ x, int n4) {
    int i = blockIdx.x * blockDim.x + threadIdx.x;
    if (i >= n4) return;
    float4 v = *(const float4*)(x + (size_t)i * 4);
    __half2 a = __floats2half2_rn(v.x, v.y), b = __floats2half2_rn(v.z, v.w);
    uint2 u;
    u.x = *(uint32_t*)&a; u.y = *(uint32_t*)&b;
    *(uint2*)(h_x + (size_t)i * 4) = u;
}

// ---------------- weights: fp32 [K][N] -> fp16 [N][K] (tiled transpose) ----------------
__global__ void __launch_bounds__(256)
transp_all_k(const float* __restrict__ wg_r, const float* __restrict__ wu_r,
             const float* __restrict__ wd_r, const float* __restrict__ wg_s,
             const float* __restrict__ wu_s, const float* __restrict__ wd_s) {
    __shared__ float ts[32][33];
    int b = blockIdx.x;
    const float* src; __half* dst; int K, N;
    if (b < 4096)        { src = wg_r; dst = h_wg_r; K = HIDDEN; N = MID_R; }
    else if (b < 8192)   { b -= 4096;  src = wu_r; dst = h_wu_r; K = HIDDEN; N = MID_R; }
    else if (b < 12288)  { b -= 8192;  src = wd_r; dst = h_wd_r; K = MID_R;  N = HIDDEN; }
    else if (b < 13312)  { b -= 12288; src = wg_s; dst = h_wg_s; K = HIDDEN; N = MID_S; }
    else if (b < 14336)  { b -= 13312; src = wu_s; dst = h_wu_s; K = HIDDEN; N = MID_S; }
    else                 { b -= 14336; src = wd_s; dst = h_wd_s; K = MID_S;  N = HIDDEN; }
    int tpe = (K / 32) * (N / 32);
    int e = b / tpe, t = b % tpe;
    int tk = t / (N / 32), tn = t % (N / 32);
    src += (size_t)e * K * N;
    dst += (size_t)e * K * N;

    int tid = threadIdx.x;
    int kr = tid >> 3, n4 = (tid & 7) << 2;
    float4 v = *(const float4*)(src + (size_t)(tk * 32 + kr) * N + tn * 32 + n4);
    ts[kr][n4 + 0] = v.x; ts[kr][n4 + 1] = v.y; ts[kr][n4 + 2] = v.z; ts[kr][n4 + 3] = v.w;
    __syncthreads();
    int nr = tid >> 3, k4 = (tid & 7) << 2;
    __half2 o0 = __floats2half2_rn(ts[k4 + 0][nr], ts[k4 + 1][nr]);
    __half2 o1 = __floats2half2_rn(ts[k4 + 2][nr], ts[k4 + 3][nr]);
    uint2 u;
    u.x = *(uint32_t*)&o0; u.y = *(uint32_t*)&o1;
    *(uint2*)(dst + (size_t)(tn * 32 + nr) * K + tk * 32 + k4) = u;
}

// ---------------- router (exact fp32; one warp per token) ----------------
__global__ void router_kernel(const float* __restrict__ x,
                              const float* __restrict__ rw, int T) {
    int warp = (blockIdx.x * blockDim.x + threadIdx.x) >> 5;
    int lane = threadIdx.x & 31;
    if (warp >= T) return;
    const float* xr = x + (size_t)warp * HIDDEN;

    float acc[NE];
#pragma unroll
    for (int e = 0; e < NE; e++) acc[e] = 0.f;

    for (int i = lane; i < HIDDEN; i += 32) {
        float xv = __ldg(xr + i);
        const float4* rp = (const float4*)(rw + (size_t)i * NE);
        float4 r0 = __ldg(rp + 0), r1 = __ldg(rp + 1);
        float4 r2 = __ldg(rp + 2), r3 = __ldg(rp + 3);
        acc[0]  += xv * r0.x; acc[1]  += xv * r0.y; acc[2]  += xv * r0.z; acc[3]  += xv * r0.w;
        acc[4]  += xv * r1.x; acc[5]  += xv * r1.y; acc[6]  += xv * r1.z; acc[7]  += xv * r1.w;
        acc[8]  += xv * r2.x; acc[9]  += xv * r2.y; acc[10] += xv * r2.z; acc[11] += xv * r2.w;
        acc[12] += xv * r3.x; acc[13] += xv * r3.y; acc[14] += xv * r3.z; acc[15] += xv * r3.w;
    }
#pragma unroll
    for (int e = 0; e < NE; e++) {
#pragma unroll
        for (int o = 16; o > 0; o >>= 1)
            acc[e] += __shfl_xor_sync(0xffffffffu, acc[e], o);
    }

    if (lane == 0) {
        float mx = acc[0];
#pragma unroll
        for (int e = 1; e < NE; e++) mx = fmaxf(mx, acc[e]);
        float p[NE], Z = 0.f;
#pragma unroll
        for (int e = 0; e < NE; e++) { p[e] = expf(acc[e] - mx); Z += p[e]; }
        int i1 = 0; float v1 = p[0];
#pragma unroll
        for (int e = 1; e < NE; e++) if (p[e] > v1) { v1 = p[e]; i1 = e; }
        int i2 = -1; float v2 = -1.f;
#pragma unroll
        for (int e = 0; e < NE; e++)
            if (e != i1 && p[e] > v2) { v2 = p[e]; i2 = e; }
        v1 /= Z; v2 /= Z;
        float s = v1 + v2 + 1e-9f;
        g_topk_idx[warp][0] = i1; g_topk_idx[warp][1] = i2;
        g_topk_w[warp][0] = v1 / s; g_topk_w[warp][1] = v2 / s;
        atomicAdd(&g_counts[i1], 1);
        atomicAdd(&g_counts[i2], 1);
    }
}

// ---------------- scan ----------------
__global__ void scan_kernel() {
    if (threadIdx.x == 0) {
        int off = 0;
        for (int e = 0; e < NE; e++) {
            g_off[e] = off;
            int c = g_counts[e];
            off += ((c + BT - 1) / BT) * BT;
        }
        g_off[NE] = off;
        for (int t = 0; t < N_TILES; t++) {
            int r = t * BT;
            int e = NE - 1;
            for (int j = 0; j < NE; j++)
                if (r >= g_off[j] && r < g_off[j + 1]) e = j;
            g_tile_expert[t] = e;
        }
    }
}

// ---------------- scatter ----------------
__global__ void scatter_kernel(int T) {
    int t = blockIdx.x * blockDim.x + threadIdx.x;
    if (t >= T) return;
#pragma unroll
    for (int k = 0; k < 2; k++) {
        int e = g_topk_idx[t][k];
        int pos = g_off[e] + atomicAdd(&g_cursor[e], 1);
        g_perm[pos] = t;
        g_pw[pos] = g_topk_w[t][k];
        g_token_pos[t][k] = pos;
    }
}

// =======================================================================
// fp16 GEMMs: 256 thr / 8 warps, 128x64 block tile, 32x32 warp tile,
// BK=32, cp.async double-buffered smem, ldmatrix fragments, mma m16n8k16.
// A smem [m][k] stride SAH; B smem [n][k] stride SBH (weights pre-transposed).
// =======================================================================

#define ABUF (BT * SAH * 2)     // bytes per A stage
#define BBUF (64 * SBH * 2)     // bytes per B stage

// ---------------- unified gate+up (routed + shared experts) ----------------
__global__ void __launch_bounds__(256)
gateup_all_k() {
    const int NBR = N_TILES * (MID_R / 64);   // 192
    int b = blockIdx.x;

    bool routed;
    int row0, col0;
    const __half* Wg; const __half* Wu;
    __half* hbase; int hstride;

    if (b < NBR) {
        routed = true;
        int tile = b >> 2;
        col0 = (b & 3) * 64;
        row0 = tile * BT;
        if (row0 >= g_off[NE]) return;
        int e = g_tile_expert[tile];
        Wg = h_wg_r + (size_t)e * MID_R * HIDDEN;
        Wu = h_wu_r + (size_t)e * MID_R * HIDDEN;
        hbase = h_Hr; hstride = MID_R;
    } else {
        routed = false;
        b -= NBR;
        int n = b >> 7;
        int rem = b & 127;
        row0 = (rem >> 3) * BT;
        col0 = (rem & 7) * 64;
        Wg = h_wg_s + (size_t)n * MID_S * HIDDEN;
        Wu = h_wu_s + (size_t)n * MID_S * HIDDEN;
        hbase = h_Hs + (size_t)n * MAX_T * MID_S; hstride = MID_S;
    }

    __shared__ __half As[2 * BT * SAH];
    __shared__ __half Bgs[2 * 64 * SBH];
    __shared__ __half Bus[2 * 64 * SBH];
    __shared__ int   s_perm[BT];
    __shared__ float s_pw[BT];

    int tid = threadIdx.x, lane = tid & 31, w = tid >> 5;
    int wr = w >> 1, wc = w & 1;
    int q2 = 2 * (lane & 3);

    const uint32_t aAs = smem_u32(As), aBg = smem_u32(Bgs), aBu = smem_u32(Bus);

    if (routed && tid < BT) {
        s_perm[tid] = g_perm[row0 + tid];
        s_pw[tid] = g_pw[row0 + tid];
    }
    __syncthreads();

    float accg[2][4][4] = {}, accu[2][4][4] = {};

#define GU_LOADS(cc, st)                                                        \
    {                                                                           \
        int kk = (cc) * 32;                                                     \
        _Pragma("unroll")                                                       \
        for (int i = 0; i < 2; i++) {                                           \
            int idx = tid + 256 * i;                                            \
            int r = idx >> 2, c8 = (idx & 3) << 3;                              \
            uint32_t d = aAs + (st) * ABUF + (r * SAH + c8) * 2;                \
            if (routed) {                                                       \
                int grow = s_perm[r];                                           \
                const __half* sp = h_x + (size_t)(grow >= 0 ? grow : 0) * HIDDEN + kk + c8; \
                int pr = grow >= 0 ? 16 : 0;                                    \
                CP16Z(d, sp, pr);                                               \
            } else {                                                            \
                CP16(d, h_x + (size_t)(row0 + r) * HIDDEN + kk + c8);           \
            }                                                                   \
        }                                                                       \
        {                                                                       \
            int n = tid >> 2, c8 = (tid & 3) << 3;                              \
            CP16(aBg + (st) * BBUF + (n * SBH + c8) * 2,                        \
                 Wg + (size_t)(col0 + n) * HIDDEN + kk + c8);                   \
            CP16(aBu + (st) * BBUF + (n * SBH + c8) * 2,                        \
                 Wu + (size_t)(col0 + n) * HIDDEN + kk + c8);                   \
        }                                                                       \
    }

    const int NCH = HIDDEN / 32;   // 32
    GU_LOADS(0, 0)
    CPCOMMIT();

    for (int c = 0; c < NCH; c++) {
        int s = c & 1;
        if (c + 1 < NCH) {
            GU_LOADS(c + 1, s ^ 1)
            CPCOMMIT();
            CPWAIT(1);
        } else {
            CPWAIT(0);
        }
        __syncthreads();

        uint32_t lrow = (lane & 15), lk = ((lane >> 4) << 3);
#pragma unroll
        for (int ks = 0; ks < 2; ks++) {
            int k0 = ks * 16;
            unsigned a[2][4], bg[2][4], bu[2][4];
#pragma unroll
            for (int rt = 0; rt < 2; rt++)
                ldsm4(a[rt], aAs + s * ABUF + ((wr * 32 + rt * 16 + lrow) * SAH + k0 + lk) * 2);
#pragma unroll
            for (int cp = 0; cp < 2; cp++) {
                ldsm4(bg[cp], aBg + s * BBUF + ((wc * 32 + cp * 16 + lrow) * SBH + k0 + lk) * 2);
                ldsm4(bu[cp], aBu + s * BBUF + ((wc * 32 + cp * 16 + lrow) * SBH + k0 + lk) * 2);
            }
#pragma unroll
            for (int rt = 0; rt < 2; rt++)
#pragma unroll
                for (int ct = 0; ct < 4; ct++) {
                    int cp = ct >> 1, wh = ct & 1;
                    unsigned bbg[2] = { bg[cp][wh], bg[cp][wh + 2] };
                    mma16(accg[rt][ct], a[rt], bbg);
                    unsigned bbu[2] = { bu[cp][wh], bu[cp][wh + 2] };
                    mma16(accu[rt][ct], a[rt], bbu);
                }
        }
        __syncthreads();
    }
#undef GU_LOADS

#pragma unroll
    for (int rt = 0; rt < 2; rt++) {
        int lr = wr * 32 + rt * 16 + (lane >> 2);
        float w0 = routed ? s_pw[lr] : 1.f;
        float w1 = routed ? s_pw[lr + 8] : 1.f;
#pragma unroll
        for (int ct = 0; ct < 4; ct++) {
            int c = col0 + wc * 32 + ct * 8 + q2;
            float* gg = accg[rt][ct];
            float* uu = accu[rt][ct];
            __half2 h0 = __floats2half2_rn(silu(gg[0]) * uu[0] * w0, silu(gg[1]) * uu[1] * w0);
            __half2 h1 = __floats2half2_rn(silu(gg[2]) * uu[2] * w1, silu(gg[3]) * uu[3] * w1);
            *(__half2*)(hbase + (size_t)(row0 + lr) * hstride + c) = h0;
            *(__half2*)(hbase + (size_t)(row0 + lr + 8) * hstride + c) = h1;
        }
    }
}

// ---------------- routed down-proj -> g_Y ----------------
__global__ void __launch_bounds__(256)
down_routed_k() {
    int tile = blockIdx.y;
    int row0 = tile * BT;
    if (row0 >= g_off[NE]) return;
    int col0 = blockIdx.x * 64;
    int e = g_tile_expert[tile];
    const __half* Wd = h_wd_r + (size_t)e * HIDDEN * MID_R;

    __shared__ __half As[2 * BT * SAH];
    __shared__ __half Bs[2 * 64 * SBH];

    int tid = threadIdx.x, lane = tid & 31, w = tid >> 5;
    int wr = w >> 1, wc = w & 1;
    int q2 = 2 * (lane & 3);

    const uint32_t aAs = smem_u32(As), aBs = smem_u32(Bs);

    float acc[2][4][4] = {};

#define DR_LOADS(cc, st)                                                        \
    {                                                                           \
        int kk = (cc) * 32;                                                     \
        _Pragma("unroll")                                                       \
        for (int i = 0; i < 2; i++) {                                           \
            int idx = tid + 256 * i;                                            \
            int r = idx >> 2, c8 = (idx & 3) << 3;                              \
            CP16(aAs + (st) * ABUF + (r * SAH + c8) * 2,                        \
                 h_Hr + (size_t)(row0 + r) * MID_R + kk + c8);                  \
        }                                                                       \
        {                                                                       \
            int n = tid >> 2, c8 = (tid & 3) << 3;                              \
            CP16(aBs + (st) * BBUF + (n * SBH + c8) * 2,                        \
                 Wd + (size_t)(col0 + n) * MID_R + kk + c8);                    \
        }                                                                       \
    }

    const int NCH = MID_R / 32;   // 8
    DR_LOADS(0, 0)
    CPCOMMIT();

    for (int c = 0; c < NCH; c++) {
        int s = c & 1;
        if (c + 1 < NCH) {
            DR_LOADS(c + 1, s ^ 1)
            CPCOMMIT();
            CPWAIT(1);
        } else {
            CPWAIT(0);
        }
        __syncthreads();

        uint32_t lrow = (lane & 15), lk = ((lane >> 4) << 3);
#pragma unroll
        for (int ks = 0; ks < 2; ks++) {
            int k0 = ks * 16;
            unsigned a[2][4], bb[2][4];
#pragma unroll
            for (int rt = 0; rt < 2; rt++)
                ldsm4(a[rt], aAs + s * ABUF + ((wr * 32 + rt * 16 + lrow) * SAH + k0 + lk) * 2);
#pragma unroll
            for (int cp = 0; cp < 2; cp++)
                ldsm4(bb[cp], aBs + s * BBUF + ((wc * 32 + cp * 16 + lrow) * SBH + k0 + lk) * 2);
#pragma unroll
            for (int rt = 0; rt < 2; rt++)
#pragma unroll
                for (int ct = 0; ct < 4; ct++) {
                    int cp = ct >> 1, wh = ct & 1;
                    unsigned bf[2] = { bb[cp][wh], bb[cp][wh + 2] };
                    mma16(acc[rt][ct], a[rt], bf);
                }
        }
        __syncthreads();
    }
#undef DR_LOADS

#pragma unroll
    for (int rt = 0; rt < 2; rt++) {
        int r0 = row0 + wr * 32 + rt * 16 + (lane >> 2);
#pragma unroll
        for (int ct = 0; ct < 4; ct++) {
            int c = col0 + wc * 32 + ct * 8 + q2;
            *(float2*)&g_Y[r0][c] = make_float2(acc[rt][ct][0], acc[rt][ct][1]);
            *(float2*)&g_Y[r0 + 8][c] = make_float2(acc[rt][ct][2], acc[rt][ct][3]);
        }
    }
}

// ---------------- shared down-proj + routed combine -> out ----------------
__global__ void __launch_bounds__(256)
down_shared_k(float* __restrict__ out) {
    int row0 = blockIdx.y * BT;
    int col0 = blockIdx.x * 64;

    __shared__ __half As[2 * BT * SAH];
    __shared__ __half Bs[2 * 64 * SBH];
    __shared__ int s_p0[BT], s_p1[BT];

    int tid = threadIdx.x, lane = tid & 31, w = tid >> 5;
    int wr = w >> 1, wc = w & 1;
    int q2 = 2 * (lane & 3);

    const uint32_t aAs = smem_u32(As), aBs = smem_u32(Bs);

    if (tid < BT) {
        s_p0[tid] = g_token_pos[row0 + tid][0];
        s_p1[tid] = g_token_pos[row0 + tid][1];
    }

    float acc[2][4][4] = {};

    const int CPE = MID_S / 32;     // 16
    const int NCH = NS * CPE;       // 32

#define DS_LOADS(cc, st)                                                        \
    {                                                                           \
        int nn = (cc) / CPE;                                                    \
        int kk = ((cc) % CPE) * 32;                                             \
        const __half* Asrc = h_Hs + (size_t)nn * MAX_T * MID_S;                 \
        const __half* Wd = h_wd_s + (size_t)nn * HIDDEN * MID_S;                \
        _Pragma("unroll")                                                       \
        for (int i = 0; i < 2; i++) {                                           \
            int idx = tid + 256 * i;                                            \
            int r = idx >> 2, c8 = (idx & 3) << 3;                              \
            CP16(aAs + (st) * ABUF + (r * SAH + c8) * 2,                        \
                 Asrc + (size_t)(row0 + r) * MID_S + kk + c8);                  \
        }                                                                       \
        {                                                                       \
            int n = tid >> 2, c8 = (tid & 3) << 3;                              \
            CP16(aBs + (st) * BBUF + (n * SBH + c8) * 2,                        \
                 Wd + (size_t)(col0 + n) * MID_S + kk + c8);                    \
        }                                                                       \
    }

    DS_LOADS(0, 0)
    CPCOMMIT();

    for (int c = 0; c < NCH; c++) {
        int s = c & 1;
        if (c + 1 < NCH) {
            DS_LOADS(c + 1, s ^ 1)
            CPCOMMIT();
            CPWAIT(1);
        } else {
            CPWAIT(0);
        }
        __syncthreads();

        uint32_t lrow = (lane & 15), lk = ((lane >> 4) << 3);
#pragma unroll
        for (int ks = 0; ks < 2; ks++) {
            int k0 = ks * 16;
            unsigned a[2][4], bb[2][4];
#pragma unroll
            for (int rt = 0; rt < 2; rt++)
                ldsm4(a[rt], aAs + s * ABUF + ((wr * 32 + rt * 16 + lrow) * SAH + k0 + lk) * 2);
#pragma unroll
            for (int cp = 0; cp < 2; cp++)
                ldsm4(bb[cp], aBs + s * BBUF + ((wc * 32 + cp * 16 + lrow) * SBH + k0 + lk) * 2);
#pragma unroll
            for (int rt = 0; rt < 2; rt++)
#pragma unroll
                for (int ct = 0; ct < 4; ct++) {
                    int cp = ct >> 1, wh = ct & 1;
                    unsigned bf[2] = { bb[cp][wh], bb[cp][wh + 2] };
                    mma16(acc[rt][ct], a[rt], bf);
                }
        }
        __syncthreads();
    }
#undef DS_LOADS

#pragma unroll
    for (int rt = 0; rt < 2; rt++) {
        int lr = wr * 32 + rt * 16 + (lane >> 2);
        int r0 = row0 + lr;
        int p0a = s_p0[lr], p1a = s_p1[lr];
        int p0b = s_p0[lr + 8], p1b = s_p1[lr + 8];
#pragma unroll
        for (int ct = 0; ct < 4; ct++) {
            int c = col0 + wc * 32 + ct * 8 + q2;
            float2 ya = *(const float2*)&g_Y[p0a][c];
            float2 yb = *(const float2*)&g_Y[p1a][c];
            *(float2*)(out + (size_t)r0 * HIDDEN + c) =
                make_float2(acc[rt][ct][0] + ya.x + yb.x,
                            acc[rt][ct][1] + ya.y + yb.y);
            float2 yc = *(const float2*)&g_Y[p0b][c];
            float2 yd = *(const float2*)&g_Y[p1b][c];
            *(float2*)(out + (size_t)(r0 + 8) * HIDDEN + c) =
                make_float2(acc[rt][ct][2] + yc.x + yd.x,
                            acc[rt][ct][3] + yc.y + yd.y);
        }
    }
}

// ---------------- launch ----------------
extern "C" void kernel_launch(void* const* d_in, const int* in_sizes, int n_in,
                              void* d_out, int out_size) {
    const float* x    = (const float*)d_in[0];
    const float* rw   = (const float*)d_in[1];
    const float* wg_r = (const float*)d_in[2];
    const float* wu_r = (const float*)d_in[3];
    const float* wd_r = (const float*)d_in[4];
    const float* wg_s = (const float*)d_in[5];
    const float* wu_s = (const float*)d_in[6];
    const float* wd_s = (const float*)d_in[7];
    float* out = (float*)d_out;

    int T = in_sizes[0] / HIDDEN;
    if (T > MAX_T || T % BT != 0) return;

    init_kernel<<<(PADDED_CAP + 255) / 256, 256>>>();
    convert_x_k<<<(T * HIDDEN / 4 + 255) / 256, 256>>>(x, T * HIDDEN / 4);
    transp_all_k<<<15360, 256>>>(wg_r, wu_r, wd_r, wg_s, wu_s, wd_s);
    router_kernel<<<(T + 7) / 8, 256>>>(x, rw, T);
    scan_kernel<<<1, 32>>>();
    scatter_kernel<<<(T + 255) / 256, 256>>>(T);

    int nb_gateup = N_TILES * (MID_R / 64)                 // 192 routed
                  + NS * (T / BT) * (MID_S / 64);          // 256 shared
    gateup_all_k<<<nb_gateup, 256>>>();

    dim3 gdr(HIDDEN / 64, N_TILES);
    down_routed_k<<<gdr, 256>>>();

    dim3 gds(HIDDEN / 64, T / BT);
    down_shared_k<<<gds, 256>>>(out);
}

// round 8
// speedup vs baseline: 4.5532x; 1.1096x over previous
#include <cuda_runtime.h>
#include <cuda_fp16.h>
#include <math.h>
#include <stdint.h>

#define HIDDEN 1024
#define NE 16
#define NS 2
#define MID_R 256
#define MID_S 512
#define MAX_T 2048
#define BT 128
#define PADDED_CAP (MAX_T * 2 + NE * BT)    // 6144
#define N_TILES (PADDED_CAP / BT)           // 48

#define SAH 72            // smem row stride in halves (144B: 16B-aligned, ldmatrix conflict-free)
#define ASTG (128 * SAH * 2)   // bytes per A stage
#define BSTG (64 * SAH * 2)    // bytes per B stage
#define GU_SMEM (2 * ASTG + 4 * BSTG + 1024)
#define DN_SMEM (2 * ASTG + 2 * BSTG + 1024)

// ---------------- device scratch ----------------
__device__ __half h_x[MAX_T * HIDDEN];
__device__ __half h_wg_r[NE * MID_R * HIDDEN];   // [e][n][k]
__device__ __half h_wu_r[NE * MID_R * HIDDEN];
__device__ __half h_wd_r[NE * HIDDEN * MID_R];
__device__ __half h_wg_s[NS * MID_S * HIDDEN];
__device__ __half h_wu_s[NS * MID_S * HIDDEN];
__device__ __half h_wd_s[NS * HIDDEN * MID_S];
__device__ __half h_Hr[PADDED_CAP * MID_R];
__device__ __half h_Hs[NS * MAX_T * MID_S];
__device__ float  g_Y[PADDED_CAP][HIDDEN];
__device__ int    g_topk_idx[MAX_T][2];
__device__ float  g_topk_w[MAX_T][2];
__device__ int    g_counts[NE];
__device__ int    g_off[NE + 1];
__device__ int    g_cursor[NE];
__device__ int    g_perm[PADDED_CAP];
__device__ float  g_pw[PADDED_CAP];
__device__ int    g_token_pos[MAX_T][2];
__device__ int    g_tile_expert[N_TILES];

// ---------------- helpers ----------------
__device__ __forceinline__ void mma16(float* c, const unsigned* a, const unsigned* b) {
    asm volatile(
        "mma.sync.aligned.m16n8k16.row.col.f32.f16.f16.f32 "
        "{%0,%1,%2,%3},{%4,%5,%6,%7},{%8,%9},{%0,%1,%2,%3};"
        : "+f"(c[0]), "+f"(c[1]), "+f"(c[2]), "+f"(c[3])
        : "r"(a[0]), "r"(a[1]), "r"(a[2]), "r"(a[3]), "r"(b[0]), "r"(b[1]));
}

__device__ __forceinline__ void ldsm4(unsigned* r, uint32_t a) {
    asm volatile("ldmatrix.sync.aligned.m8n8.x4.shared.b16 {%0,%1,%2,%3}, [%4];"
                 : "=r"(r[0]), "=r"(r[1]), "=r"(r[2]), "=r"(r[3]) : "r"(a));
}

__device__ __forceinline__ uint32_t smem_u32(const void* p) {
    uint32_t a;
    asm("{ .reg .u64 t; cvta.to.shared.u64 t, %1; cvt.u32.u64 %0, t; }" : "=r"(a) : "l"(p));
    return a;
}

#define CP16(d, s)      asm volatile("cp.async.ca.shared.global [%0], [%1], 16;" :: "r"(d), "l"(s))
#define CP16Z(d, s, n)  asm volatile("cp.async.ca.shared.global [%0], [%1], 16, %2;" :: "r"(d), "l"(s), "r"(n))
#define CPCOMMIT()      asm volatile("cp.async.commit_group;")
#define CPWAIT(n)       asm volatile("cp.async.wait_group %0;" :: "n"(n))

__device__ __forceinline__ float silu(float g) { return g / (1.f + __expf(-g)); }

// ---------------- init ----------------
__global__ void init_kernel() {
    int i = blockIdx.x * blockDim.x + threadIdx.x;
    if (i < PADDED_CAP) { g_perm[i] = -1; g_pw[i] = 0.f; }
    if (i < NE) { g_counts[i] = 0; g_cursor[i] = 0; }
}

// ---------------- weights: fp32 [K][N] -> fp16 [N][K] (tiled transpose) ----------------
__global__ void __launch_bounds__(256)
transp_all_k(const float* __restrict__ wg_r, const float* __restrict__ wu_r,
             const float* __restrict__ wd_r, const float* __restrict__ wg_s,
             const float* __restrict__ wu_s, const float* __restrict__ wd_s) {
    __shared__ float ts[32][33];
    int b = blockIdx.x;
    const float* src; __half* dst; int K, N;
    if (b < 4096)        { src = wg_r; dst = h_wg_r; K = HIDDEN; N = MID_R; }
    else if (b < 8192)   { b -= 4096;  src = wu_r; dst = h_wu_r; K = HIDDEN; N = MID_R; }
    else if (b < 12288)  { b -= 8192;  src = wd_r; dst = h_wd_r; K = MID_R;  N = HIDDEN; }
    else if (b < 13312)  { b -= 12288; src = wg_s; dst = h_wg_s; K = HIDDEN; N = MID_S; }
    else if (b < 14336)  { b -= 13312; src = wu_s; dst = h_wu_s; K = HIDDEN; N = MID_S; }
    else                 { b -= 14336; src = wd_s; dst = h_wd_s; K = MID_S;  N = HIDDEN; }
    int tpe = (K / 32) * (N / 32);
    int e = b / tpe, t = b % tpe;
    int tk = t / (N / 32), tn = t % (N / 32);
    src += (size_t)e * K * N;
    dst += (size_t)e * K * N;

    int tid = threadIdx.x;
    int kr = tid >> 3, n4 = (tid & 7) << 2;
    float4 v = *(const float4*)(src + (size_t)(tk * 32 + kr) * N + tn * 32 + n4);
    ts[kr][n4 + 0] = v.x; ts[kr][n4 + 1] = v.y; ts[kr][n4 + 2] = v.z; ts[kr][n4 + 3] = v.w;
    __syncthreads();
    int nr = tid >> 3, k4 = (tid & 7) << 2;
    __half2 o0 = __floats2half2_rn(ts[k4 + 0][nr], ts[k4 + 1][nr]);
    __half2 o1 = __floats2half2_rn(ts[k4 + 2][nr], ts[k4 + 3][nr]);
    uint2 u;
    u.x = *(uint32_t*)&o0; u.y = *(uint32_t*)&o1;
    *(uint2*)(dst + (size_t)(tn * 32 + nr) * K + tk * 32 + k4) = u;
}

// ---------------- router + x->fp16 convert (4 tokens per warp) ----------------
__global__ void __launch_bounds__(256)
router_kernel(const float* __restrict__ x, const float* __restrict__ rw, int T) {
    int b = blockIdx.x;                      // 32 tokens per block
    int tid = threadIdx.x, lane = tid & 31, w = tid >> 5;

    // phase 1: convert this block's 32 token rows to fp16 (coalesced float4)
    const float4* xb = (const float4*)(x + (size_t)b * 32 * HIDDEN);
    __half* hb = h_x + (size_t)b * 32 * HIDDEN;
#pragma unroll
    for (int i = 0; i < 32; i++) {
        int idx = tid + 256 * i;
        float4 v = __ldg(xb + idx);
        __half2 p0 = __floats2half2_rn(v.x, v.y), p1 = __floats2half2_rn(v.z, v.w);
        uint2 u;
        u.x = *(uint32_t*)&p0; u.y = *(uint32_t*)&p1;
        *(uint2*)(hb + (size_t)idx * 4) = u;
    }

    // phase 2: logits for 4 tokens per warp (amortizes rw reads 4x)
    int tok0 = b * 32 + w * 4;
    const float* x0 = x + (size_t)tok0 * HIDDEN;

    float acc[4][NE];
#pragma unroll
    for (int t = 0; t < 4; t++)
#pragma unroll
        for (int e = 0; e < NE; e++) acc[t][e] = 0.f;

    for (int i = lane; i < HIDDEN; i += 32) {
        const float4* rp = (const float4*)(rw + (size_t)i * NE);
        float4 r0 = __ldg(rp + 0), r1 = __ldg(rp + 1);
        float4 r2 = __ldg(rp + 2), r3 = __ldg(rp + 3);
        float xs[4];
#pragma unroll
        for (int t = 0; t < 4; t++) xs[t] = __ldg(x0 + (size_t)t * HIDDEN + i);
#pragma unroll
        for (int t = 0; t < 4; t++) {
            float xv = xs[t];
            acc[t][0]  += xv * r0.x; acc[t][1]  += xv * r0.y; acc[t][2]  += xv * r0.z; acc[t][3]  += xv * r0.w;
            acc[t][4]  += xv * r1.x; acc[t][5]  += xv * r1.y; acc[t][6]  += xv * r1.z; acc[t][7]  += xv * r1.w;
            acc[t][8]  += xv * r2.x; acc[t][9]  += xv * r2.y; acc[t][10] += xv * r2.z; acc[t][11] += xv * r2.w;
            acc[t][12] += xv * r3.x; acc[t][13] += xv * r3.y; acc[t][14] += xv * r3.z; acc[t][15] += xv * r3.w;
        }
    }
#pragma unroll
    for (int t = 0; t < 4; t++)
#pragma unroll
        for (int e = 0; e < NE; e++)
#pragma unroll
            for (int o = 16; o > 0; o >>= 1)
                acc[t][e] += __shfl_xor_sync(0xffffffffu, acc[t][e], o);

    if (lane == 0) {
#pragma unroll
        for (int t = 0; t < 4; t++) {
            int tok = tok0 + t;
            float mx = acc[t][0];
#pragma unroll
            for (int e = 1; e < NE; e++) mx = fmaxf(mx, acc[t][e]);
            float p[NE], Z = 0.f;
#pragma unroll
            for (int e = 0; e < NE; e++) { p[e] = expf(acc[t][e] - mx); Z += p[e]; }
            int i1 = 0; float v1 = p[0];
#pragma unroll
            for (int e = 1; e < NE; e++) if (p[e] > v1) { v1 = p[e]; i1 = e; }
            int i2 = -1; float v2 = -1.f;
#pragma unroll
            for (int e = 0; e < NE; e++)
                if (e != i1 && p[e] > v2) { v2 = p[e]; i2 = e; }
            v1 /= Z; v2 /= Z;
            float s = v1 + v2 + 1e-9f;
            g_topk_idx[tok][0] = i1; g_topk_idx[tok][1] = i2;
            g_topk_w[tok][0] = v1 / s; g_topk_w[tok][1] = v2 / s;
            atomicAdd(&g_counts[i1], 1);
            atomicAdd(&g_counts[i2], 1);
        }
    }
}

// ---------------- scan ----------------
__global__ void scan_kernel() {
    if (threadIdx.x == 0) {
        int off = 0;
        for (int e = 0; e < NE; e++) {
            g_off[e] = off;
            int c = g_counts[e];
            off += ((c + BT - 1) / BT) * BT;
        }
        g_off[NE] = off;
        for (int t = 0; t < N_TILES; t++) {
            int r = t * BT;
            int e = NE - 1;
            for (int j = 0; j < NE; j++)
                if (r >= g_off[j] && r < g_off[j + 1]) e = j;
            g_tile_expert[t] = e;
        }
    }
}

// ---------------- scatter ----------------
__global__ void scatter_kernel(int T) {
    int t = blockIdx.x * blockDim.x + threadIdx.x;
    if (t >= T) return;
#pragma unroll
    for (int k = 0; k < 2; k++) {
        int e = g_topk_idx[t][k];
        int pos = g_off[e] + atomicAdd(&g_cursor[e], 1);
        g_perm[pos] = t;
        g_pw[pos] = g_topk_w[t][k];
        g_token_pos[t][k] = pos;
    }
}

// =======================================================================
// fp16 GEMMs: 256 thr / 8 warps, 128x64 block tile, 32x32 warp tile,
// BK=64 chunks, cp.async double-buffered dynamic smem, ldmatrix, mma16.
// A smem [m][k] stride 72h; B smem [n][k] stride 72h (weights pre-transposed).
// =======================================================================

// ---------------- unified gate+up (routed + shared experts) ----------------
__global__ void __launch_bounds__(256)
gateup_all_k() {
    const int NBR = N_TILES * (MID_R / 64);   // 192
    int b = blockIdx.x;

    bool routed;
    int row0, col0;
    const __half* Wg; const __half* Wu;
    __half* hbase; int hstride;

    if (b < NBR) {
        routed = true;
        int tile = b >> 2;
        col0 = (b & 3) * 64;
        row0 = tile * BT;
        if (row0 >= g_off[NE]) return;
        int e = g_tile_expert[tile];
        Wg = h_wg_r + (size_t)e * MID_R * HIDDEN;
        Wu = h_wu_r + (size_t)e * MID_R * HIDDEN;
        hbase = h_Hr; hstride = MID_R;
    } else {
        routed = false;
        b -= NBR;
        int n = b >> 7;
        int rem = b & 127;
        row0 = (rem >> 3) * BT;
        col0 = (rem & 7) * 64;
        Wg = h_wg_s + (size_t)n * MID_S * HIDDEN;
        Wu = h_wu_s + (size_t)n * MID_S * HIDDEN;
        hbase = h_Hs + (size_t)n * MAX_T * MID_S; hstride = MID_S;
    }

    extern __shared__ char dsm[];
    const uint32_t aAs = smem_u32(dsm);
    const uint32_t aBg = aAs + 2 * ASTG;
    const uint32_t aBu = aBg + 2 * BSTG;
    int*   s_perm = (int*)(dsm + 2 * ASTG + 4 * BSTG);
    float* s_pw   = (float*)(dsm + 2 * ASTG + 4 * BSTG + 512);

    int tid = threadIdx.x, lane = tid & 31, w = tid >> 5;
    int wr = w >> 1, wc = w & 1;
    int q2 = 2 * (lane & 3);

    if (routed && tid < BT) {
        s_perm[tid] = g_perm[row0 + tid];
        s_pw[tid] = g_pw[row0 + tid];
    }
    __syncthreads();

    float accg[2][4][4] = {}, accu[2][4][4] = {};

#define GU_LOADS(cc, st)                                                        \
    {                                                                           \
        int kk = (cc) * 64;                                                     \
        _Pragma("unroll")                                                       \
        for (int i = 0; i < 4; i++) {                                           \
            int idx = tid + 256 * i;                                            \
            int r = idx >> 3, c8 = (idx & 7) << 3;                              \
            uint32_t d = aAs + (st) * ASTG + (r * SAH + c8) * 2;                \
            if (routed) {                                                       \
                int grow = s_perm[r];                                           \
                const __half* sp = h_x + (size_t)(grow >= 0 ? grow : 0) * HIDDEN + kk + c8; \
                int pr = grow >= 0 ? 16 : 0;                                    \
                CP16Z(d, sp, pr);                                               \
            } else {                                                            \
                CP16(d, h_x + (size_t)(row0 + r) * HIDDEN + kk + c8);           \
            }                                                                   \
        }                                                                       \
        _Pragma("unroll")                                                       \
        for (int i = 0; i < 2; i++) {                                           \
            int idx = tid + 256 * i;                                            \
            int n = idx >> 3, c8 = (idx & 7) << 3;                              \
            CP16(aBg + (st) * BSTG + (n * SAH + c8) * 2,                        \
                 Wg + (size_t)(col0 + n) * HIDDEN + kk + c8);                   \
            CP16(aBu + (st) * BSTG + (n * SAH + c8) * 2,                        \
                 Wu + (size_t)(col0 + n) * HIDDEN + kk + c8);                   \
        }                                                                       \
    }

    const int NCH = HIDDEN / 64;   // 16
    GU_LOADS(0, 0)
    CPCOMMIT();

    for (int c = 0; c < NCH; c++) {
        int s = c & 1;
        if (c + 1 < NCH) {
            GU_LOADS(c + 1, s ^ 1)
            CPCOMMIT();
            CPWAIT(1);
        } else {
            CPWAIT(0);
        }
        __syncthreads();

        uint32_t lrow = (lane & 15), lk = ((lane >> 4) << 3);
#pragma unroll
        for (int ks = 0; ks < 4; ks++) {
            int k0 = ks * 16;
            unsigned a[2][4], bg[2][4], bu[2][4];
#pragma unroll
            for (int rt = 0; rt < 2; rt++)
                ldsm4(a[rt], aAs + s * ASTG + ((wr * 32 + rt * 16 + lrow) * SAH + k0 + lk) * 2);
#pragma unroll
            for (int cp = 0; cp < 2; cp++) {
                ldsm4(bg[cp], aBg + s * BSTG + ((wc * 32 + cp * 16 + lrow) * SAH + k0 + lk) * 2);
                ldsm4(bu[cp], aBu + s * BSTG + ((wc * 32 + cp * 16 + lrow) * SAH + k0 + lk) * 2);
            }
#pragma unroll
            for (int rt = 0; rt < 2; rt++)
#pragma unroll
                for (int ct = 0; ct < 4; ct++) {
                    int cp = ct >> 1, wh = ct & 1;
                    unsigned bbg[2] = { bg[cp][wh], bg[cp][wh + 2] };
                    mma16(accg[rt][ct], a[rt], bbg);
                    unsigned bbu[2] = { bu[cp][wh], bu[cp][wh + 2] };
                    mma16(accu[rt][ct], a[rt], bbu);
                }
        }
        __syncthreads();
    }
#undef GU_LOADS

#pragma unroll
    for (int rt = 0; rt < 2; rt++) {
        int lr = wr * 32 + rt * 16 + (lane >> 2);
        float w0 = routed ? s_pw[lr] : 1.f;
        float w1 = routed ? s_pw[lr + 8] : 1.f;
#pragma unroll
        for (int ct = 0; ct < 4; ct++) {
            int c = col0 + wc * 32 + ct * 8 + q2;
            float* gg = accg[rt][ct];
            float* uu = accu[rt][ct];
            __half2 h0 = __floats2half2_rn(silu(gg[0]) * uu[0] * w0, silu(gg[1]) * uu[1] * w0);
            __half2 h1 = __floats2half2_rn(silu(gg[2]) * uu[2] * w1, silu(gg[3]) * uu[3] * w1);
            *(__half2*)(hbase + (size_t)(row0 + lr) * hstride + c) = h0;
            *(__half2*)(hbase + (size_t)(row0 + lr + 8) * hstride + c) = h1;
        }
    }
}

// ---------------- routed down-proj -> g_Y ----------------
__global__ void __launch_bounds__(256)
down_routed_k() {
    int tile = blockIdx.y;
    int row0 = tile * BT;
    if (row0 >= g_off[NE]) return;
    int col0 = blockIdx.x * 64;
    int e = g_tile_expert[tile];
    const __half* Wd = h_wd_r + (size_t)e * HIDDEN * MID_R;

    extern __shared__ char dsm[];
    const uint32_t aAs = smem_u32(dsm);
    const uint32_t aBs = aAs + 2 * ASTG;

    int tid = threadIdx.x, lane = tid & 31, w = tid >> 5;
    int wr = w >> 1, wc = w & 1;
    int q2 = 2 * (lane & 3);

    float acc[2][4][4] = {};

#define DR_LOADS(cc, st)                                                        \
    {                                                                           \
        int kk = (cc) * 64;                                                     \
        _Pragma("unroll")                                                       \
        for (int i = 0; i < 4; i++) {                                           \
            int idx = tid + 256 * i;                                            \
            int r = idx >> 3, c8 = (idx & 7) << 3;                              \
            CP16(aAs + (st) * ASTG + (r * SAH + c8) * 2,                        \
                 h_Hr + (size_t)(row0 + r) * MID_R + kk + c8);                  \
        }                                                                       \
        _Pragma("unroll")                                                       \
        for (int i = 0; i < 2; i++) {                                           \
            int idx = tid + 256 * i;                                            \
            int n = idx >> 3, c8 = (idx & 7) << 3;                              \
            CP16(aBs + (st) * BSTG + (n * SAH + c8) * 2,                        \
                 Wd + (size_t)(col0 + n) * MID_R + kk + c8);                    \
        }                                                                       \
    }

    const int NCH = MID_R / 64;   // 4
    DR_LOADS(0, 0)
    CPCOMMIT();

    for (int c = 0; c < NCH; c++) {
        int s = c & 1;
        if (c + 1 < NCH) {
            DR_LOADS(c + 1, s ^ 1)
            CPCOMMIT();
            CPWAIT(1);
        } else {
            CPWAIT(0);
        }
        __syncthreads();

        uint32_t lrow = (lane & 15), lk = ((lane >> 4) << 3);
#pragma unroll
        for (int ks = 0; ks < 4; ks++) {
            int k0 = ks * 16;
            unsigned a[2][4], bb[2][4];
#pragma unroll
            for (int rt = 0; rt < 2; rt++)
                ldsm4(a[rt], aAs + s * ASTG + ((wr * 32 + rt * 16 + lrow) * SAH + k0 + lk) * 2);
#pragma unroll
            for (int cp = 0; cp < 2; cp++)
                ldsm4(bb[cp], aBs + s * BSTG + ((wc * 32 + cp * 16 + lrow) * SAH + k0 + lk) * 2);
#pragma unroll
            for (int rt = 0; rt < 2; rt++)
#pragma unroll
                for (int ct = 0; ct < 4; ct++) {
                    int cp = ct >> 1, wh = ct & 1;
                    unsigned bf[2] = { bb[cp][wh], bb[cp][wh + 2] };
                    mma16(acc[rt][ct], a[rt], bf);
                }
        }
        __syncthreads();
    }
#undef DR_LOADS

#pragma unroll
    for (int rt = 0; rt < 2; rt++) {
        int r0 = row0 + wr * 32 + rt * 16 + (lane >> 2);
#pragma unroll
        for (int ct = 0; ct < 4; ct++) {
            int c = col0 + wc * 32 + ct * 8 + q2;
            *(float2*)&g_Y[r0][c] = make_float2(acc[rt][ct][0], acc[rt][ct][1]);
            *(float2*)&g_Y[r0 + 8][c] = make_float2(acc[rt][ct][2], acc[rt][ct][3]);
        }
    }
}

// ---------------- shared down-proj + routed combine -> out ----------------
__global__ void __launch_bounds__(256)
down_shared_k(float* __restrict__ out) {
    int row0 = blockIdx.y * BT;
    int col0 = blockIdx.x * 64;

    extern __shared__ char dsm[];
    const uint32_t aAs = smem_u32(dsm);
    const uint32_t aBs = aAs + 2 * ASTG;
    int* s_p0 = (int*)(dsm + 2 * ASTG + 2 * BSTG);
    int* s_p1 = (int*)(dsm + 2 * ASTG + 2 * BSTG + 512);

    int tid = threadIdx.x, lane = tid & 31, w = tid >> 5;
    int wr = w >> 1, wc = w & 1;
    int q2 = 2 * (lane & 3);

    if (tid < BT) {
        s_p0[tid] = g_token_pos[row0 + tid][0];
        s_p1[tid] = g_token_pos[row0 + tid][1];
    }

    float acc[2][4][4] = {};

    const int CPE = MID_S / 64;     // 8
    const int NCH = NS * CPE;       // 16

#define DS_LOADS(cc, st)                                                        \
    {                                                                           \
        int nn = (cc) / CPE;                                                    \
        int kk = ((cc) % CPE) * 64;                                             \
        const __half* Asrc = h_Hs + (size_t)nn * MAX_T * MID_S;                 \
        const __half* Wd = h_wd_s + (size_t)nn * HIDDEN * MID_S;                \
        _Pragma("unroll")                                                       \
        for (int i = 0; i < 4; i++) {                                           \
            int idx = tid + 256 * i;                                            \
            int r = idx >> 3, c8 = (idx & 7) << 3;                              \
            CP16(aAs + (st) * ASTG + (r * SAH + c8) * 2,                        \
                 Asrc + (size_t)(row0 + r) * MID_S + kk + c8);                  \
        }                                                                       \
        _Pragma("unroll")                                                       \
        for (int i = 0; i < 2; i++) {                                           \
            int idx = tid + 256 * i;                                            \
            int n = idx >> 3, c8 = (idx & 7) << 3;                              \
            CP16(aBs + (st) * BSTG + (n * SAH + c8) * 2,                        \
                 Wd + (size_t)(col0 + n) * MID_S + kk + c8);                    \
        }                                                                       \
    }

    DS_LOADS(0, 0)
    CPCOMMIT();

    for (int c = 0; c < NCH; c++) {
        int s = c & 1;
        if (c + 1 < NCH) {
            DS_LOADS(c + 1, s ^ 1)
            CPCOMMIT();
            CPWAIT(1);
        } else {
            CPWAIT(0);
        }
        __syncthreads();

        uint32_t lrow = (lane & 15), lk = ((lane >> 4) << 3);
#pragma unroll
        for (int ks = 0; ks < 4; ks++) {
            int k0 = ks * 16;
            unsigned a[2][4], bb[2][4];
#pragma unroll
            for (int rt = 0; rt < 2; rt++)
                ldsm4(a[rt], aAs + s * ASTG + ((wr * 32 + rt * 16 + lrow) * SAH + k0 + lk) * 2);
#pragma unroll
            for (int cp = 0; cp < 2; cp++)
                ldsm4(bb[cp], aBs + s * BSTG + ((wc * 32 + cp * 16 + lrow) * SAH + k0 + lk) * 2);
#pragma unroll
            for (int rt = 0; rt < 2; rt++)
#pragma unroll
                for (int ct = 0; ct < 4; ct++) {
                    int cp = ct >> 1, wh = ct & 1;
                    unsigned bf[2] = { bb[cp][wh], bb[cp][wh + 2] };
                    mma16(acc[rt][ct], a[rt], bf);
                }
        }
        __syncthreads();
    }
#undef DS_LOADS

#pragma unroll
    for (int rt = 0; rt < 2; rt++) {
        int lr = wr * 32 + rt * 16 + (lane >> 2);
        int r0 = row0 + lr;
        int p0a = s_p0[lr], p1a = s_p1[lr];
        int p0b = s_p0[lr + 8], p1b = s_p1[lr + 8];
#pragma unroll
        for (int ct = 0; ct < 4; ct++) {
            int c = col0 + wc * 32 + ct * 8 + q2;
            float2 ya = *(const float2*)&g_Y[p0a][c];
            float2 yb = *(const float2*)&g_Y[p1a][c];
            *(float2*)(out + (size_t)r0 * HIDDEN + c) =
                make_float2(acc[rt][ct][0] + ya.x + yb.x,
                            acc[rt][ct][1] + ya.y + yb.y);
            float2 yc = *(const float2*)&g_Y[p0b][c];
            float2 yd = *(const float2*)&g_Y[p1b][c];
            *(float2*)(out + (size_t)(r0 + 8) * HIDDEN + c) =
                make_float2(acc[rt][ct][2] + yc.x + yd.x,
                            acc[rt][ct][3] + yc.y + yd.y);
        }
    }
}

// ---------------- launch ----------------
extern "C" void kernel_launch(void* const* d_in, const int* in_sizes, int n_in,
                              void* d_out, int out_size) {
    const float* x    = (const float*)d_in[0];
    const float* rw   = (const float*)d_in[1];
    const float* wg_r = (const float*)d_in[2];
    const float* wu_r = (const float*)d_in[3];
    const float* wd_r = (const float*)d_in[4];
    const float* wg_s = (const float*)d_in[5];
    const float* wu_s = (const float*)d_in[6];
    const float* wd_s = (const float*)d_in[7];
    float* out = (float*)d_out;

    int T = in_sizes[0] / HIDDEN;
    if (T > MAX_T || T % BT != 0) return;

    cudaFuncSetAttribute(gateup_all_k, cudaFuncAttributeMaxDynamicSharedMemorySize, GU_SMEM);
    cudaFuncSetAttribute(down_routed_k, cudaFuncAttributeMaxDynamicSharedMemorySize, DN_SMEM);
    cudaFuncSetAttribute(down_shared_k, cudaFuncAttributeMaxDynamicSharedMemorySize, DN_SMEM);

    init_kernel<<<(PADDED_CAP + 255) / 256, 256>>>();
    router_kernel<<<T / 32, 256>>>(x, rw, T);
    scan_kernel<<<1, 32>>>();
    scatter_kernel<<<(T + 255) / 256, 256>>>(T);
    transp_all_k<<<15360, 256>>>(wg_r, wu_r, wd_r, wg_s, wu_s, wd_s);

    int nb_gateup = N_TILES * (MID_R / 64)                 // 192 routed
                  + NS * (T / BT) * (MID_S / 64);          // 256 shared
    gateup_all_k<<<nb_gateup, 256, GU_SMEM>>>();

    dim3 gdr(HIDDEN / 64, N_TILES);
    down_routed_k<<<gdr, 256, DN_SMEM>>>();

    dim3 gds(HIDDEN / 64, T / BT);
    down_shared_k<<<gds, 256, DN_SMEM>>>(out);
}

// round 9
// speedup vs baseline: 4.6763x; 1.0270x over previous
#include <cuda_runtime.h>
#include <cuda_fp16.h>
#include <math.h>
#include <stdint.h>

#define HIDDEN 1024
#define NE 16
#define NS 2
#define MID_R 256
#define MID_S 512
#define MAX_T 2048
#define BT 128
#define PADDED_CAP (MAX_T * 2 + NE * BT)    // 6144
#define N_TILES (PADDED_CAP / BT)           // 48

#define SAH 72            // smem row stride in halves (144B: 16B-aligned, ldmatrix conflict-free)
#define ASTG (128 * SAH * 2)   // bytes per A stage
#define BSTG (64 * SAH * 2)    // bytes per B stage
#define GU_SMEM (2 * ASTG + 4 * BSTG + 1024)
#define DN_SMEM (2 * ASTG + 2 * BSTG + 1024)

// ---------------- device scratch ----------------
__device__ __half h_x[MAX_T * HIDDEN];
__device__ __half h_wg_r[NE * MID_R * HIDDEN];   // [e][n][k]
__device__ __half h_wu_r[NE * MID_R * HIDDEN];
__device__ __half h_wd_r[NE * HIDDEN * MID_R];
__device__ __half h_wg_s[NS * MID_S * HIDDEN];
__device__ __half h_wu_s[NS * MID_S * HIDDEN];
__device__ __half h_wd_s[NS * HIDDEN * MID_S];
__device__ __half h_Hr[PADDED_CAP * MID_R];
__device__ __half h_Hs[NS * MAX_T * MID_S];
__device__ float  g_Y[PADDED_CAP][HIDDEN];
__device__ int    g_topk_idx[MAX_T][2];
__device__ float  g_topk_w[MAX_T][2];
__device__ int    g_off[NE + 1];
__device__ int    g_perm[PADDED_CAP];
__device__ float  g_pw[PADDED_CAP];
__device__ int    g_token_pos[MAX_T][2];
__device__ int    g_tile_expert[N_TILES];

// ---------------- helpers ----------------
__device__ __forceinline__ void mma16(float* c, const unsigned* a, const unsigned* b) {
    asm volatile(
        "mma.sync.aligned.m16n8k16.row.col.f32.f16.f16.f32 "
        "{%0,%1,%2,%3},{%4,%5,%6,%7},{%8,%9},{%0,%1,%2,%3};"
        : "+f"(c[0]), "+f"(c[1]), "+f"(c[2]), "+f"(c[3])
        : "r"(a[0]), "r"(a[1]), "r"(a[2]), "r"(a[3]), "r"(b[0]), "r"(b[1]));
}

__device__ __forceinline__ void ldsm4(unsigned* r, uint32_t a) {
    asm volatile("ldmatrix.sync.aligned.m8n8.x4.shared.b16 {%0,%1,%2,%3}, [%4];"
                 : "=r"(r[0]), "=r"(r[1]), "=r"(r[2]), "=r"(r[3]) : "r"(a));
}

__device__ __forceinline__ uint32_t smem_u32(const void* p) {
    uint32_t a;
    asm("{ .reg .u64 t; cvta.to.shared.u64 t, %1; cvt.u32.u64 %0, t; }" : "=r"(a) : "l"(p));
    return a;
}

#define CP16(d, s)      asm volatile("cp.async.ca.shared.global [%0], [%1], 16;" :: "r"(d), "l"(s))
#define CP16Z(d, s, n)  asm volatile("cp.async.ca.shared.global [%0], [%1], 16, %2;" :: "r"(d), "l"(s), "r"(n))
#define CPCOMMIT()      asm volatile("cp.async.commit_group;")
#define CPWAIT(n)       asm volatile("cp.async.wait_group %0;" :: "n"(n))

__device__ __forceinline__ float silu(float g) { return g / (1.f + __expf(-g)); }

// ---------------- router + x->fp16 convert (4 tokens per warp; no atomics) ----------------
__global__ void __launch_bounds__(256)
router_kernel(const float* __restrict__ x, const float* __restrict__ rw, int T) {
    int b = blockIdx.x;                      // 32 tokens per block
    int tid = threadIdx.x, lane = tid & 31, w = tid >> 5;

    // phase 1: convert this block's 32 token rows to fp16 (coalesced float4)
    const float4* xb = (const float4*)(x + (size_t)b * 32 * HIDDEN);
    __half* hb = h_x + (size_t)b * 32 * HIDDEN;
#pragma unroll
    for (int i = 0; i < 32; i++) {
        int idx = tid + 256 * i;
        float4 v = __ldg(xb + idx);
        __half2 p0 = __floats2half2_rn(v.x, v.y), p1 = __floats2half2_rn(v.z, v.w);
        uint2 u;
        u.x = *(uint32_t*)&p0; u.y = *(uint32_t*)&p1;
        *(uint2*)(hb + (size_t)idx * 4) = u;
    }

    // phase 2: logits for 4 tokens per warp
    int tok0 = b * 32 + w * 4;
    const float* x0 = x + (size_t)tok0 * HIDDEN;

    float acc[4][NE];
#pragma unroll
    for (int t = 0; t < 4; t++)
#pragma unroll
        for (int e = 0; e < NE; e++) acc[t][e] = 0.f;

    for (int i = lane; i < HIDDEN; i += 32) {
        const float4* rp = (const float4*)(rw + (size_t)i * NE);
        float4 r0 = __ldg(rp + 0), r1 = __ldg(rp + 1);
        float4 r2 = __ldg(rp + 2), r3 = __ldg(rp + 3);
        float xs[4];
#pragma unroll
        for (int t = 0; t < 4; t++) xs[t] = __ldg(x0 + (size_t)t * HIDDEN + i);
#pragma unroll
        for (int t = 0; t < 4; t++) {
            float xv = xs[t];
            acc[t][0]  += xv * r0.x; acc[t][1]  += xv * r0.y; acc[t][2]  += xv * r0.z; acc[t][3]  += xv * r0.w;
            acc[t][4]  += xv * r1.x; acc[t][5]  += xv * r1.y; acc[t][6]  += xv * r1.z; acc[t][7]  += xv * r1.w;
            acc[t][8]  += xv * r2.x; acc[t][9]  += xv * r2.y; acc[t][10] += xv * r2.z; acc[t][11] += xv * r2.w;
            acc[t][12] += xv * r3.x; acc[t][13] += xv * r3.y; acc[t][14] += xv * r3.z; acc[t][15] += xv * r3.w;
        }
    }
#pragma unroll
    for (int t = 0; t < 4; t++)
#pragma unroll
        for (int e = 0; e < NE; e++)
#pragma unroll
            for (int o = 16; o > 0; o >>= 1)
                acc[t][e] += __shfl_xor_sync(0xffffffffu, acc[t][e], o);

    if (lane == 0) {
#pragma unroll
        for (int t = 0; t < 4; t++) {
            int tok = tok0 + t;
            float mx = acc[t][0];
#pragma unroll
            for (int e = 1; e < NE; e++) mx = fmaxf(mx, acc[t][e]);
            float p[NE], Z = 0.f;
#pragma unroll
            for (int e = 0; e < NE; e++) { p[e] = expf(acc[t][e] - mx); Z += p[e]; }
            int i1 = 0; float v1 = p[0];
#pragma unroll
            for (int e = 1; e < NE; e++) if (p[e] > v1) { v1 = p[e]; i1 = e; }
            int i2 = -1; float v2 = -1.f;
#pragma unroll
            for (int e = 0; e < NE; e++)
                if (e != i1 && p[e] > v2) { v2 = p[e]; i2 = e; }
            v1 /= Z; v2 /= Z;
            float s = v1 + v2 + 1e-9f;
            g_topk_idx[tok][0] = i1; g_topk_idx[tok][1] = i2;
            g_topk_w[tok][0] = v1 / s; g_topk_w[tok][1] = v2 / s;
        }
    }
}

// ---------------- fused dispatch: histogram + offsets + tile map + pad init + scatter ----------------
__global__ void __launch_bounds__(1024)
dispatch_k(int T) {
    __shared__ int sc[NE];
    __shared__ int soff[NE + 1];
    __shared__ int scur[NE];

    int tid = threadIdx.x;
    if (tid < NE) { sc[tid] = 0; scur[tid] = 0; }
    __syncthreads();

    for (int t = tid; t < T; t += 1024) {
        atomicAdd(&sc[g_topk_idx[t][0]], 1);
        atomicAdd(&sc[g_topk_idx[t][1]], 1);
    }
    __syncthreads();

    if (tid == 0) {
        int off = 0;
        for (int e = 0; e < NE; e++) {
            soff[e] = off;
            off += ((sc[e] + BT - 1) / BT) * BT;
        }
        soff[NE] = off;
    }
    __syncthreads();

    if (tid < NE + 1) g_off[tid] = soff[tid];
    if (tid < N_TILES) {
        int r = tid * BT;
        int e = NE - 1;
        for (int j = 0; j < NE; j++)
            if (r >= soff[j] && r < soff[j + 1]) e = j;
        g_tile_expert[tid] = e;
    }
    // blanket pad init (scatter overwrites live slots after the barrier)
    for (int i = tid; i < PADDED_CAP; i += 1024) { g_perm[i] = -1; g_pw[i] = 0.f; }
    __syncthreads();

    for (int t = tid; t < T; t += 1024) {
#pragma unroll
        for (int k = 0; k < 2; k++) {
            int e = g_topk_idx[t][k];
            int pos = soff[e] + atomicAdd(&scur[e], 1);
            g_perm[pos] = t;
            g_pw[pos] = g_topk_w[t][k];
            g_token_pos[t][k] = pos;
        }
    }
}

// ---------------- weights: fp32 [K][N] -> fp16 [N][K] (tiled transpose) ----------------
__global__ void __launch_bounds__(256)
transp_all_k(const float* __restrict__ wg_r, const float* __restrict__ wu_r,
             const float* __restrict__ wd_r, const float* __restrict__ wg_s,
             const float* __restrict__ wu_s, const float* __restrict__ wd_s) {
    __shared__ float ts[32][33];
    int b = blockIdx.x;
    const float* src; __half* dst; int K, N;
    if (b < 4096)        { src = wg_r; dst = h_wg_r; K = HIDDEN; N = MID_R; }
    else if (b < 8192)   { b -= 4096;  src = wu_r; dst = h_wu_r; K = HIDDEN; N = MID_R; }
    else if (b < 12288)  { b -= 8192;  src = wd_r; dst = h_wd_r; K = MID_R;  N = HIDDEN; }
    else if (b < 13312)  { b -= 12288; src = wg_s; dst = h_wg_s; K = HIDDEN; N = MID_S; }
    else if (b < 14336)  { b -= 13312; src = wu_s; dst = h_wu_s; K = HIDDEN; N = MID_S; }
    else                 { b -= 14336; src = wd_s; dst = h_wd_s; K = MID_S;  N = HIDDEN; }
    int tpe = (K / 32) * (N / 32);
    int e = b / tpe, t = b % tpe;
    int tk = t / (N / 32), tn = t % (N / 32);
    src += (size_t)e * K * N;
    dst += (size_t)e * K * N;

    int tid = threadIdx.x;
    int kr = tid >> 3, n4 = (tid & 7) << 2;
    float4 v = *(const float4*)(src + (size_t)(tk * 32 + kr) * N + tn * 32 + n4);
    ts[kr][n4 + 0] = v.x; ts[kr][n4 + 1] = v.y; ts[kr][n4 + 2] = v.z; ts[kr][n4 + 3] = v.w;
    __syncthreads();
    int nr = tid >> 3, k4 = (tid & 7) << 2;
    __half2 o0 = __floats2half2_rn(ts[k4 + 0][nr], ts[k4 + 1][nr]);
    __half2 o1 = __floats2half2_rn(ts[k4 + 2][nr], ts[k4 + 3][nr]);
    uint2 u;
    u.x = *(uint32_t*)&o0; u.y = *(uint32_t*)&o1;
    *(uint2*)(dst + (size_t)(tn * 32 + nr) * K + tk * 32 + k4) = u;
}

// =======================================================================
// fp16 GEMMs: 256 thr / 8 warps, 128x64 block tile, 32x32 warp tile,
// BK=64 chunks, cp.async double-buffered dynamic smem, ldmatrix, mma16.
// =======================================================================

// ---------------- unified gate+up (routed + shared experts) ----------------
__global__ void __launch_bounds__(256)
gateup_all_k() {
    const int NBR = N_TILES * (MID_R / 64);   // 192
    int b = blockIdx.x;

    bool routed;
    int row0, col0;
    const __half* Wg; const __half* Wu;
    __half* hbase; int hstride;

    if (b < NBR) {
        routed = true;
        int tile = b >> 2;
        col0 = (b & 3) * 64;
        row0 = tile * BT;
        if (row0 >= g_off[NE]) return;
        int e = g_tile_expert[tile];
        Wg = h_wg_r + (size_t)e * MID_R * HIDDEN;
        Wu = h_wu_r + (size_t)e * MID_R * HIDDEN;
        hbase = h_Hr; hstride = MID_R;
    } else {
        routed = false;
        b -= NBR;
        int n = b >> 7;
        int rem = b & 127;
        row0 = (rem >> 3) * BT;
        col0 = (rem & 7) * 64;
        Wg = h_wg_s + (size_t)n * MID_S * HIDDEN;
        Wu = h_wu_s + (size_t)n * MID_S * HIDDEN;
        hbase = h_Hs + (size_t)n * MAX_T * MID_S; hstride = MID_S;
    }

    extern __shared__ char dsm[];
    const uint32_t aAs = smem_u32(dsm);
    const uint32_t aBg = aAs + 2 * ASTG;
    const uint32_t aBu = aBg + 2 * BSTG;
    int*   s_perm = (int*)(dsm + 2 * ASTG + 4 * BSTG);
    float* s_pw   = (float*)(dsm + 2 * ASTG + 4 * BSTG + 512);

    int tid = threadIdx.x, lane = tid & 31, w = tid >> 5;
    int wr = w >> 1, wc = w & 1;
    int q2 = 2 * (lane & 3);

    if (routed && tid < BT) {
        s_perm[tid] = g_perm[row0 + tid];
        s_pw[tid] = g_pw[row0 + tid];
    }
    __syncthreads();

    float accg[2][4][4] = {}, accu[2][4][4] = {};

#define GU_LOADS(cc, st)                                                        \
    {                                                                           \
        int kk = (cc) * 64;                                                     \
        _Pragma("unroll")                                                       \
        for (int i = 0; i < 4; i++) {                                           \
            int idx = tid + 256 * i;                                            \
            int r = idx >> 3, c8 = (idx & 7) << 3;                              \
            uint32_t d = aAs + (st) * ASTG + (r * SAH + c8) * 2;                \
            if (routed) {                                                       \
                int grow = s_perm[r];                                           \
                const __half* sp = h_x + (size_t)(grow >= 0 ? grow : 0) * HIDDEN + kk + c8; \
                int pr = grow >= 0 ? 16 : 0;                                    \
                CP16Z(d, sp, pr);                                               \
            } else {                                                            \
                CP16(d, h_x + (size_t)(row0 + r) * HIDDEN + kk + c8);           \
            }                                                                   \
        }                                                                       \
        _Pragma("unroll")                                                       \
        for (int i = 0; i < 2; i++) {                                           \
            int idx = tid + 256 * i;                                            \
            int n = idx >> 3, c8 = (idx & 7) << 3;                              \
            CP16(aBg + (st) * BSTG + (n * SAH + c8) * 2,                        \
                 Wg + (size_t)(col0 + n) * HIDDEN + kk + c8);                   \
            CP16(aBu + (st) * BSTG + (n * SAH + c8) * 2,                        \
                 Wu + (size_t)(col0 + n) * HIDDEN + kk + c8);                   \
        }                                                                       \
    }

    const int NCH = HIDDEN / 64;   // 16
    GU_LOADS(0, 0)
    CPCOMMIT();

    for (int c = 0; c < NCH; c++) {
        int s = c & 1;
        if (c + 1 < NCH) {
            GU_LOADS(c + 1, s ^ 1)
            CPCOMMIT();
            CPWAIT(1);
        } else {
            CPWAIT(0);
        }
        __syncthreads();

        uint32_t lrow = (lane & 15), lk = ((lane >> 4) << 3);
#pragma unroll
        for (int ks = 0; ks < 4; ks++) {
            int k0 = ks * 16;
            unsigned a[2][4], bg[2][4], bu[2][4];
#pragma unroll
            for (int rt = 0; rt < 2; rt++)
                ldsm4(a[rt], aAs + s * ASTG + ((wr * 32 + rt * 16 + lrow) * SAH + k0 + lk) * 2);
#pragma unroll
            for (int cp = 0; cp < 2; cp++) {
                ldsm4(bg[cp], aBg + s * BSTG + ((wc * 32 + cp * 16 + lrow) * SAH + k0 + lk) * 2);
                ldsm4(bu[cp], aBu + s * BSTG + ((wc * 32 + cp * 16 + lrow) * SAH + k0 + lk) * 2);
            }
#pragma unroll
            for (int rt = 0; rt < 2; rt++)
#pragma unroll
                for (int ct = 0; ct < 4; ct++) {
                    int cp = ct >> 1, wh = ct & 1;
                    unsigned bbg[2] = { bg[cp][wh], bg[cp][wh + 2] };
                    mma16(accg[rt][ct], a[rt], bbg);
                    unsigned bbu[2] = { bu[cp][wh], bu[cp][wh + 2] };
                    mma16(accu[rt][ct], a[rt], bbu);
                }
        }
        __syncthreads();
    }
#undef GU_LOADS

#pragma unroll
    for (int rt = 0; rt < 2; rt++) {
        int lr = wr * 32 + rt * 16 + (lane >> 2);
        float w0 = routed ? s_pw[lr] : 1.f;
        float w1 = routed ? s_pw[lr + 8] : 1.f;
#pragma unroll
        for (int ct = 0; ct < 4; ct++) {
            int c = col0 + wc * 32 + ct * 8 + q2;
            float* gg = accg[rt][ct];
            float* uu = accu[rt][ct];
            __half2 h0 = __floats2half2_rn(silu(gg[0]) * uu[0] * w0, silu(gg[1]) * uu[1] * w0);
            __half2 h1 = __floats2half2_rn(silu(gg[2]) * uu[2] * w1, silu(gg[3]) * uu[3] * w1);
            *(__half2*)(hbase + (size_t)(row0 + lr) * hstride + c) = h0;
            *(__half2*)(hbase + (size_t)(row0 + lr + 8) * hstride + c) = h1;
        }
    }
}

// ---------------- routed down-proj -> g_Y ----------------
__global__ void __launch_bounds__(256)
down_routed_k() {
    int tile = blockIdx.y;
    int row0 = tile * BT;
    if (row0 >= g_off[NE]) return;
    int col0 = blockIdx.x * 64;
    int e = g_tile_expert[tile];
    const __half* Wd = h_wd_r + (size_t)e * HIDDEN * MID_R;

    extern __shared__ char dsm[];
    const uint32_t aAs = smem_u32(dsm);
    const uint32_t aBs = aAs + 2 * ASTG;

    int tid = threadIdx.x, lane = tid & 31, w = tid >> 5;
    int wr = w >> 1, wc = w & 1;
    int q2 = 2 * (lane & 3);

    float acc[2][4][4] = {};

#define DR_LOADS(cc, st)                                                        \
    {                                                                           \
        int kk = (cc) * 64;                                                     \
        _Pragma("unroll")                                                       \
        for (int i = 0; i < 4; i++) {                                           \
            int idx = tid + 256 * i;                                            \
            int r = idx >> 3, c8 = (idx & 7) << 3;                              \
            CP16(aAs + (st) * ASTG + (r * SAH + c8) * 2,                        \
                 h_Hr + (size_t)(row0 + r) * MID_R + kk + c8);                  \
        }                                                                       \
        _Pragma("unroll")                                                       \
        for (int i = 0; i < 2; i++) {                                           \
            int idx = tid + 256 * i;                                            \
            int n = idx >> 3, c8 = (idx & 7) << 3;                              \
            CP16(aBs + (st) * BSTG + (n * SAH + c8) * 2,                        \
                 Wd + (size_t)(col0 + n) * MID_R + kk + c8);                    \
        }                                                                       \
    }

    const int NCH = MID_R / 64;   // 4
    DR_LOADS(0, 0)
    CPCOMMIT();

    for (int c = 0; c < NCH; c++) {
        int s = c & 1;
        if (c + 1 < NCH) {
            DR_LOADS(c + 1, s ^ 1)
            CPCOMMIT();
            CPWAIT(1);
        } else {
            CPWAIT(0);
        }
        __syncthreads();

        uint32_t lrow = (lane & 15), lk = ((lane >> 4) << 3);
#pragma unroll
        for (int ks = 0; ks < 4; ks++) {
            int k0 = ks * 16;
            unsigned a[2][4], bb[2][4];
#pragma unroll
            for (int rt = 0; rt < 2; rt++)
                ldsm4(a[rt], aAs + s * ASTG + ((wr * 32 + rt * 16 + lrow) * SAH + k0 + lk) * 2);
#pragma unroll
            for (int cp = 0; cp < 2; cp++)
                ldsm4(bb[cp], aBs + s * BSTG + ((wc * 32 + cp * 16 + lrow) * SAH + k0 + lk) * 2);
#pragma unroll
            for (int rt = 0; rt < 2; rt++)
#pragma unroll
                for (int ct = 0; ct < 4; ct++) {
                    int cp = ct >> 1, wh = ct & 1;
                    unsigned bf[2] = { bb[cp][wh], bb[cp][wh + 2] };
                    mma16(acc[rt][ct], a[rt], bf);
                }
        }
        __syncthreads();
    }
#undef DR_LOADS

#pragma unroll
    for (int rt = 0; rt < 2; rt++) {
        int r0 = row0 + wr * 32 + rt * 16 + (lane >> 2);
#pragma unroll
        for (int ct = 0; ct < 4; ct++) {
            int c = col0 + wc * 32 + ct * 8 + q2;
            *(float2*)&g_Y[r0][c] = make_float2(acc[rt][ct][0], acc[rt][ct][1]);
            *(float2*)&g_Y[r0 + 8][c] = make_float2(acc[rt][ct][2], acc[rt][ct][3]);
        }
    }
}

// ---------------- shared down-proj + routed combine -> out ----------------
__global__ void __launch_bounds__(256)
down_shared_k(float* __restrict__ out) {
    int row0 = blockIdx.y * BT;
    int col0 = blockIdx.x * 64;

    extern __shared__ char dsm[];
    const uint32_t aAs = smem_u32(dsm);
    const uint32_t aBs = aAs + 2 * ASTG;
    int* s_p0 = (int*)(dsm + 2 * ASTG + 2 * BSTG);
    int* s_p1 = (int*)(dsm + 2 * ASTG + 2 * BSTG + 512);

    int tid = threadIdx.x, lane = tid & 31, w = tid >> 5;
    int wr = w >> 1, wc = w & 1;
    int q2 = 2 * (lane & 3);

    if (tid < BT) {
        s_p0[tid] = g_token_pos[row0 + tid][0];
        s_p1[tid] = g_token_pos[row0 + tid][1];
    }

    float acc[2][4][4] = {};

    const int CPE = MID_S / 64;     // 8
    const int NCH = NS * CPE;       // 16

#define DS_LOADS(cc, st)                                                        \
    {                                                                           \
        int nn = (cc) / CPE;                                                    \
        int kk = ((cc) % CPE) * 64;                                             \
        const __half* Asrc = h_Hs + (size_t)nn * MAX_T * MID_S;                 \
        const __half* Wd = h_wd_s + (size_t)nn * HIDDEN * MID_S;                \
        _Pragma("unroll")                                                       \
        for (int i = 0; i < 4; i++) {                                           \
            int idx = tid + 256 * i;                                            \
            int r = idx >> 3, c8 = (idx & 7) << 3;                              \
            CP16(aAs + (st) * ASTG + (r * SAH + c8) * 2,                        \
                 Asrc + (size_t)(row0 + r) * MID_S + kk + c8);                  \
        }                                                                       \
        _Pragma("unroll")                                                       \
        for (int i = 0; i < 2; i++) {                                           \
            int idx = tid + 256 * i;                                            \
            int n = idx >> 3, c8 = (idx & 7) << 3;                              \
            CP16(aBs + (st) * BSTG + (n * SAH + c8) * 2,                        \
                 Wd + (size_t)(col0 + n) * MID_S + kk + c8);                    \
        }                                                                       \
    }

    DS_LOADS(0, 0)
    CPCOMMIT();

    for (int c = 0; c < NCH; c++) {
        int s = c & 1;
        if (c + 1 < NCH) {
            DS_LOADS(c + 1, s ^ 1)
            CPCOMMIT();
            CPWAIT(1);
        } else {
            CPWAIT(0);
        }
        __syncthreads();

        uint32_t lrow = (lane & 15), lk = ((lane >> 4) << 3);
#pragma unroll
        for (int ks = 0; ks < 4; ks++) {
            int k0 = ks * 16;
            unsigned a[2][4], bb[2][4];
#pragma unroll
            for (int rt = 0; rt < 2; rt++)
                ldsm4(a[rt], aAs + s * ASTG + ((wr * 32 + rt * 16 + lrow) * SAH + k0 + lk) * 2);
#pragma unroll
            for (int cp = 0; cp < 2; cp++)
                ldsm4(bb[cp], aBs + s * BSTG + ((wc * 32 + cp * 16 + lrow) * SAH + k0 + lk) * 2);
#pragma unroll
            for (int rt = 0; rt < 2; rt++)
#pragma unroll
                for (int ct = 0; ct < 4; ct++) {
                    int cp = ct >> 1, wh = ct & 1;
                    unsigned bf[2] = { bb[cp][wh], bb[cp][wh + 2] };
                    mma16(acc[rt][ct], a[rt], bf);
                }
        }
        __syncthreads();
    }
#undef DS_LOADS

#pragma unroll
    for (int rt = 0; rt < 2; rt++) {
        int lr = wr * 32 + rt * 16 + (lane >> 2);
        int r0 = row0 + lr;
        int p0a = s_p0[lr], p1a = s_p1[lr];
        int p0b = s_p0[lr + 8], p1b = s_p1[lr + 8];
#pragma unroll
        for (int ct = 0; ct < 4; ct++) {
            int c = col0 + wc * 32 + ct * 8 + q2;
            float2 ya = *(const float2*)&g_Y[p0a][c];
            float2 yb = *(const float2*)&g_Y[p1a][c];
            *(float2*)(out + (size_t)r0 * HIDDEN + c) =
                make_float2(acc[rt][ct][0] + ya.x + yb.x,
                            acc[rt][ct][1] + ya.y + yb.y);
            float2 yc = *(const float2*)&g_Y[p0b][c];
            float2 yd = *(const float2*)&g_Y[p1b][c];
            *(float2*)(out + (size_t)(r0 + 8) * HIDDEN + c) =
                make_float2(acc[rt][ct][2] + yc.x + yd.x,
                            acc[rt][ct][3] + yc.y + yd.y);
        }
    }
}

// ---------------- launch ----------------
extern "C" void kernel_launch(void* const* d_in, const int* in_sizes, int n_in,
                              void* d_out, int out_size) {
    const float* x    = (const float*)d_in[0];
    const float* rw   = (const float*)d_in[1];
    const float* wg_r = (const float*)d_in[2];
    const float* wu_r = (const float*)d_in[3];
    const float* wd_r = (const float*)d_in[4];
    const float* wg_s = (const float*)d_in[5];
    const float* wu_s = (const float*)d_in[6];
    const float* wd_s = (const float*)d_in[7];
    float* out = (float*)d_out;

    int T = in_sizes[0] / HIDDEN;
    if (T > MAX_T || T % BT != 0) return;

    cudaFuncSetAttribute(gateup_all_k, cudaFuncAttributeMaxDynamicSharedMemorySize, GU_SMEM);
    cudaFuncSetAttribute(down_routed_k, cudaFuncAttributeMaxDynamicSharedMemorySize, DN_SMEM);
    cudaFuncSetAttribute(down_shared_k, cudaFuncAttributeMaxDynamicSharedMemorySize, DN_SMEM);

    router_kernel<<<T / 32, 256>>>(x, rw, T);
    dispatch_k<<<1, 1024>>>(T);
    transp_all_k<<<15360, 256>>>(wg_r, wu_r, wd_r, wg_s, wu_s, wd_s);

    int nb_gateup = N_TILES * (MID_R / 64)                 // 192 routed
                  + NS * (T / BT) * (MID_S / 64);          // 256 shared
    gateup_all_k<<<nb_gateup, 256, GU_SMEM>>>();           // our 4th launch -> ncu -s 5 lands here

    dim3 gdr(HIDDEN / 64, N_TILES);
    down_routed_k<<<gdr, 256, DN_SMEM>>>();

    dim3 gds(HIDDEN / 64, T / BT);
    down_shared_k<<<gds, 256, DN_SMEM>>>(out);
}